// round 9
// baseline (speedup 1.0000x reference)
#include <cuda_runtime.h>
#include <cuda_bf16.h>
#include <math.h>
#include <stdint.h>

// Problem constants: bs=2, seq=2048, d_model=512, heads=8, d_k=64
#define DM     512
#define HEADS  8
#define DK     64
#define SEQ    2048
#define BS     2
#define TOK    (SEQ*BS)     // 4096

// ---------------- scratch (device globals; no allocations allowed) -------------
__device__ float g_Q[TOK * DM];
__device__ float g_K[TOK * DM];
__device__ float g_V[TOK * DM];
__device__ __nv_bfloat16 g_ahi[3 * TOK * DM];
__device__ __nv_bfloat16 g_alo[3 * TOK * DM];
__device__ __nv_bfloat16 g_wthi[4][DM * DM];   // transposed weights [N,K], hi part
__device__ __nv_bfloat16 g_wtlo[4][DM * DM];   // lo part
__device__ float g_vsum[BS * DM];

struct WIn  { const float* W[4]; };
struct CIn  { const float* x[3]; };
struct GOut { float* C[3]; const float* bias[3]; };

// ================= helpers ======================================================
__device__ __forceinline__ uint32_t smem_u32(const void* p) {
    uint32_t a;
    asm("{ .reg .u64 t; cvta.to.shared.u64 t, %1; cvt.u32.u64 %0, t; }" : "=r"(a) : "l"(p));
    return a;
}
__device__ __forceinline__ uint32_t sw128(uint32_t o) { return o ^ ((o >> 3) & 0x70); }

__device__ __forceinline__ void cp16(uint32_t dst, const void* src) {
    asm volatile("cp.async.cg.shared.global [%0], [%1], 16;" :: "r"(dst), "l"(src));
}
__device__ __forceinline__ void ldsm4(uint32_t* r, uint32_t addr) {
    asm volatile("ldmatrix.sync.aligned.m8n8.x4.shared.b16 {%0,%1,%2,%3}, [%4];"
        : "=r"(r[0]), "=r"(r[1]), "=r"(r[2]), "=r"(r[3]) : "r"(addr));
}
__device__ __forceinline__ void mma16816(float* c, const uint32_t* a, uint32_t b0, uint32_t b1) {
    asm volatile("mma.sync.aligned.m16n8k16.row.col.f32.bf16.bf16.f32 "
        "{%0,%1,%2,%3}, {%4,%5,%6,%7}, {%8,%9}, {%0,%1,%2,%3};"
        : "+f"(c[0]), "+f"(c[1]), "+f"(c[2]), "+f"(c[3])
        : "r"(a[0]), "r"(a[1]), "r"(a[2]), "r"(a[3]), "r"(b0), "r"(b1));
}

// ================= bf16-split mma.sync GEMM ====================================
// C[M=TOK, N=DM] = (Ahi+Alo)[M,K] @ (Bhi+Blo)^T + bias, with B stored [N,K].
// CTA tile 128x128, K chunk 64 (128-byte SW128 rows), 2-stage cp.async pipeline.
// grid.z batches independent GEMMs. z == vsum_z additionally accumulates the
// per-batch column sums of its output tile into g_vsum (post-bias).
#define KC      64
#define NKC     (DM / KC)               // 8
#define TILE_B  (128 * 128)             // 16 KB per array per stage
#define STG_B   (4 * TILE_B)            // 64 KB per stage
#define GEMM_SMEM (2 * STG_B)           // 131072

__global__ void __launch_bounds__(256, 1)
gemm_mma(const __nv_bfloat16* __restrict__ Ahi_base, const __nv_bfloat16* __restrict__ Alo_base,
         const __nv_bfloat16* __restrict__ Whi_base, const __nv_bfloat16* __restrict__ Wlo_base,
         GOut outs, int vsum_z)
{
    extern __shared__ char smem[];
    const uint32_t sb = smem_u32(smem);
    const int tid  = threadIdx.x;
    const int wid  = tid >> 5;
    const int lane = tid & 31;
    const int m0   = blockIdx.y * 128;
    const int n0   = blockIdx.x * 128;
    const int z    = blockIdx.z;

    const __nv_bfloat16* arrs[4] = {
        Ahi_base + (size_t)z * TOK * DM, Alo_base + (size_t)z * TOK * DM,
        Whi_base + (size_t)z * DM * DM,  Wlo_base + (size_t)z * DM * DM };
    float* C = outs.C[z];
    const float* bias = outs.bias[z];

    // cp.async mapping: thread -> row tid/2, four 16B chunks (tid&1)*4 .. +3
    const int lrow = tid >> 1;
    const int lc0  = (tid & 1) * 4;

    auto load_stage = [&](int kc, int s) {
        const uint32_t stg = sb + s * STG_B;
        #pragma unroll
        for (int a = 0; a < 4; a++) {
            const int grow = ((a < 2) ? m0 : n0) + lrow;
            const __nv_bfloat16* src = arrs[a] + (size_t)grow * DM + kc * KC + lc0 * 8;
            const uint32_t abase = stg + a * TILE_B;
            #pragma unroll
            for (int c = 0; c < 4; c++)
                cp16(abase + sw128(lrow * 128 + (lc0 + c) * 16), src + c * 8);
        }
        asm volatile("cp.async.commit_group;" ::: "memory");
    };

    load_stage(0, 0);
    load_stage(1, 1);

    // warp tiling: warp tile 64(m) x 32(n)
    const int wm = (wid & 1) * 64;
    const int wn = (wid >> 1) * 32;
    const int lane8 = lane & 7;
    const int rowp8 = ((lane >> 3) & 1) * 8;
    const int kp1   = (lane >> 4) & 1;

    float acc[4][4][4];
    #pragma unroll
    for (int f = 0; f < 4; f++)
        #pragma unroll
        for (int n = 0; n < 4; n++)
            #pragma unroll
            for (int e = 0; e < 4; e++) acc[f][n][e] = 0.f;

    for (int kc = 0; kc < NKC; kc++) {
        const int s = kc & 1;
        if (kc < NKC - 1) asm volatile("cp.async.wait_group 1;" ::: "memory");
        else              asm volatile("cp.async.wait_group 0;" ::: "memory");
        __syncthreads();

        const uint32_t sAh = sb + s * STG_B + 0 * TILE_B;
        const uint32_t sAl = sb + s * STG_B + 1 * TILE_B;
        const uint32_t sBh = sb + s * STG_B + 2 * TILE_B;
        const uint32_t sBl = sb + s * STG_B + 3 * TILE_B;

        #pragma unroll
        for (int kk = 0; kk < KC / 16; kk++) {
            const int ch = kk * 2 + kp1;
            // hoist all fragment loads for this k-step
            uint32_t bh[2][4], bl[2][4];
            #pragma unroll
            for (int p = 0; p < 2; p++) {
                const uint32_t off = sw128((wn + p * 16 + lane8 + rowp8) * 128 + ch * 16);
                ldsm4(bh[p], sBh + off);
                ldsm4(bl[p], sBl + off);
            }
            uint32_t ah[4][4], al[4][4];
            #pragma unroll
            for (int f = 0; f < 4; f++) {
                const uint32_t off = sw128((wm + f * 16 + lane8 + rowp8) * 128 + ch * 16);
                ldsm4(ah[f], sAh + off);
                ldsm4(al[f], sAl + off);
            }
            #pragma unroll
            for (int f = 0; f < 4; f++) {
                #pragma unroll
                for (int p = 0; p < 2; p++) {
                    mma16816(acc[f][2 * p + 0], ah[f], bh[p][0], bh[p][2]);
                    mma16816(acc[f][2 * p + 1], ah[f], bh[p][1], bh[p][3]);
                    mma16816(acc[f][2 * p + 0], ah[f], bl[p][0], bl[p][2]);
                    mma16816(acc[f][2 * p + 1], ah[f], bl[p][1], bl[p][3]);
                    mma16816(acc[f][2 * p + 0], al[f], bh[p][0], bh[p][2]);
                    mma16816(acc[f][2 * p + 1], al[f], bh[p][1], bh[p][3]);
                }
            }
        }
        __syncthreads();
        if (kc + 2 < NKC) load_stage(kc + 2, s);
    }

    // epilogue (post-bias values), optional fused column-sum for V
    const int row0 = m0 + wm + (lane >> 2);
    const int colb = n0 + wn + (lane & 3) * 2;
    float cs0[4], cs1[4];   // per-thread column partial sums (post-bias)
    #pragma unroll
    for (int n = 0; n < 4; n++) { cs0[n] = 0.f; cs1[n] = 0.f; }

    #pragma unroll
    for (int f = 0; f < 4; f++) {
        #pragma unroll
        for (int n = 0; n < 4; n++) {
            const int col = colb + n * 8;
            const float2 bv = *(const float2*)(bias + col);
            float2 o0, o1;
            o0.x = acc[f][n][0] + bv.x; o0.y = acc[f][n][1] + bv.y;
            o1.x = acc[f][n][2] + bv.x; o1.y = acc[f][n][3] + bv.y;
            cs0[n] += o0.x + o1.x;
            cs1[n] += o0.y + o1.y;
            *(float2*)(C + (size_t)(row0 + f * 16 + 0) * DM + col) = o0;
            *(float2*)(C + (size_t)(row0 + f * 16 + 8) * DM + col) = o1;
        }
    }

    if (z == vsum_z) {
        // reduce across the 8 lanes that share (lane & 3): xor lane bits 2,3,4
        #pragma unroll
        for (int n = 0; n < 4; n++) {
            #pragma unroll
            for (int o = 4; o <= 16; o <<= 1) {
                cs0[n] += __shfl_xor_sync(0xffffffffu, cs0[n], o);
                cs1[n] += __shfl_xor_sync(0xffffffffu, cs1[n], o);
            }
        }
        if (lane < 4) {
            const int b = m0 / SEQ;
            #pragma unroll
            for (int n = 0; n < 4; n++) {
                const int col = n0 + wn + (lane & 3) * 2 + n * 8;
                atomicAdd(&g_vsum[b * DM + col + 0], cs0[n]);
                atomicAdd(&g_vsum[b * DM + col + 1], cs1[n]);
            }
        }
    }
}

// ================= conversion kernels ==========================================
// fp32 -> (hi, lo) bf16 split; grid.y selects source, output offset y*TOK*DM/4
__global__ void conv_act(CIn in, __nv_bfloat16* __restrict__ hi, __nv_bfloat16* __restrict__ lo)
{
    const int z = blockIdx.y;
    const size_t i = (size_t)blockIdx.x * blockDim.x + threadIdx.x;   // over float4s
    const size_t o = (size_t)z * (TOK * DM / 4) + i;
    float4 v = ((const float4*)in.x[z])[i];
    __nv_bfloat16 h[4], l[4];
    float f[4] = { v.x, v.y, v.z, v.w };
    #pragma unroll
    for (int t = 0; t < 4; t++) {
        h[t] = __float2bfloat16_rn(f[t]);
        l[t] = __float2bfloat16_rn(f[t] - __bfloat162float(h[t]));
    }
    ((ushort4*)hi)[o] = make_ushort4(__bfloat16_as_ushort(h[0]), __bfloat16_as_ushort(h[1]),
                                     __bfloat16_as_ushort(h[2]), __bfloat16_as_ushort(h[3]));
    ((ushort4*)lo)[o] = make_ushort4(__bfloat16_as_ushort(l[0]), __bfloat16_as_ushort(l[1]),
                                     __bfloat16_as_ushort(l[2]), __bfloat16_as_ushort(l[3]));
}

// W [K,N] fp32 row-major -> Wt [N,K] bf16 hi/lo (transposed); grid.z selects weight.
// Block (0,0,0) also zeroes g_vsum for the fused V column-sum.
__global__ void wt_all(WIn in, __nv_bfloat16* __restrict__ hi, __nv_bfloat16* __restrict__ lo)
{
    __shared__ float t[32][33];
    const int z = blockIdx.z;
    const float* W = in.W[z];
    __nv_bfloat16* ho = hi + (size_t)z * DM * DM;
    __nv_bfloat16* lo2 = lo + (size_t)z * DM * DM;
    const int bx = blockIdx.x * 32;   // n
    const int by = blockIdx.y * 32;   // k
    const int x = threadIdx.x, y = threadIdx.y;
    const int tid = y * 32 + x;

    if (z == 0 && blockIdx.x == 0 && blockIdx.y == 0) {
        #pragma unroll
        for (int r = 0; r < BS * DM / 256; r++) g_vsum[tid + r * 256] = 0.f;
    }

    #pragma unroll
    for (int r = y; r < 32; r += 8)
        t[r][x] = W[(size_t)(by + r) * DM + bx + x];
    __syncthreads();
    #pragma unroll
    for (int i = y; i < 32; i += 8) {
        float v = t[x][i];
        __nv_bfloat16 h = __float2bfloat16_rn(v);
        __nv_bfloat16 l = __float2bfloat16_rn(v - __bfloat162float(h));
        size_t o = (size_t)(bx + i) * DM + by + x;
        ho[o] = h;
        lo2[o] = l;
    }
}

// ================= banded attention (closed-form full-row softmax) ==============
// 4 lanes per row (16 dims/lane), 8 rows per warp. Writes ctx directly as
// bf16 hi/lo into the GEMM activation buffers (slot 0).
__global__ __launch_bounds__(256)
void attn_kernel(const float* __restrict__ Q, const float* __restrict__ K,
                 const float* __restrict__ V,
                 __nv_bfloat16* __restrict__ chi, __nv_bfloat16* __restrict__ clo)
{
    const int lane = threadIdx.x & 31;
    const int wid  = threadIdx.x >> 5;
    const int sub  = lane >> 2;          // row within warp (0..7)
    const int sl   = lane & 3;           // dim slice (0..3), 16 floats each

    const int row_id = (blockIdx.x * 8 + wid) * 8 + sub;
    const int i  = row_id & (SEQ - 1);
    const int bh = row_id >> 11;         // SEQ = 2^11
    const int h  = bh & (HEADS - 1);
    const int b  = bh >> 3;

    const size_t base = ((size_t)b * SEQ) * DM + h * DK + sl * 16;

    float4 qv[4];
    {
        const float* qp = Q + base + (size_t)i * DM;
        #pragma unroll
        for (int c = 0; c < 4; c++) qv[c] = *(const float4*)(qp + c * 4);
    }

    const int jlo = max(i - 4, 0);
    const int jhi = min(i + 4, SEQ - 1);
    const int nb  = jhi - jlo + 1;

    float s[9], smax = 0.f;   // implicit zeros outside band participate in max
    #pragma unroll
    for (int t = 0; t < 9; t++) {
        const int j = jlo + t;
        const bool valid = (j <= jhi);
        const int jc = valid ? j : jhi;
        const float* kp = K + base + (size_t)jc * DM;
        float p = 0.f;
        #pragma unroll
        for (int c = 0; c < 4; c++) {
            float4 kv = *(const float4*)(kp + c * 4);
            p += qv[c].x * kv.x + qv[c].y * kv.y + qv[c].z * kv.z + qv[c].w * kv.w;
        }
        p += __shfl_xor_sync(0xffffffffu, p, 1);
        p += __shfl_xor_sync(0xffffffffu, p, 2);
        const int mn = min(i, j), mx = max(i, j);
        const int clo2 = max(mx - 2, 0);
        const int chi2 = min(mn + 2, SEQ - 1);
        const float cc = (float)(chi2 - clo2 + 1);
        s[t] = valid ? p * 0.125f * cc : -1e30f;
        smax = fmaxf(smax, s[t]);
    }

    const float w0 = expf(-smax);
    float Z = (float)(SEQ - nb) * w0;
    float w[9];
    #pragma unroll
    for (int t = 0; t < 9; t++) { w[t] = expf(s[t] - smax); Z += w[t]; }
    const float rZ = 1.f / Z;

    float4 acc[4];
    #pragma unroll
    for (int c = 0; c < 4; c++) { acc[c].x = 0.f; acc[c].y = 0.f; acc[c].z = 0.f; acc[c].w = 0.f; }

    #pragma unroll
    for (int t = 0; t < 9; t++) {
        const int j = jlo + t;
        const bool valid = (j <= jhi);
        const int jc = valid ? j : jhi;
        const float wt = valid ? (w[t] - w0) : 0.f;
        const float* vp = V + base + (size_t)jc * DM;
        #pragma unroll
        for (int c = 0; c < 4; c++) {
            float4 vv = *(const float4*)(vp + c * 4);
            acc[c].x += wt * vv.x; acc[c].y += wt * vv.y;
            acc[c].z += wt * vv.z; acc[c].w += wt * vv.w;
        }
    }

    const float* vsp = g_vsum + b * DM + h * DK + sl * 16;
    const size_t o = base + (size_t)i * DM;
    #pragma unroll
    for (int c = 0; c < 4; c++) {
        float4 vs = *(const float4*)(vsp + c * 4);
        float r[4];
        r[0] = (acc[c].x + w0 * vs.x) * rZ;
        r[1] = (acc[c].y + w0 * vs.y) * rZ;
        r[2] = (acc[c].z + w0 * vs.z) * rZ;
        r[3] = (acc[c].w + w0 * vs.w) * rZ;
        ushort4 uh, ul;
        __nv_bfloat16 hb;
        hb = __float2bfloat16_rn(r[0]); uh.x = __bfloat16_as_ushort(hb);
        ul.x = __bfloat16_as_ushort(__float2bfloat16_rn(r[0] - __bfloat162float(hb)));
        hb = __float2bfloat16_rn(r[1]); uh.y = __bfloat16_as_ushort(hb);
        ul.y = __bfloat16_as_ushort(__float2bfloat16_rn(r[1] - __bfloat162float(hb)));
        hb = __float2bfloat16_rn(r[2]); uh.z = __bfloat16_as_ushort(hb);
        ul.z = __bfloat16_as_ushort(__float2bfloat16_rn(r[2] - __bfloat162float(hb)));
        hb = __float2bfloat16_rn(r[3]); uh.w = __bfloat16_as_ushort(hb);
        ul.w = __bfloat16_as_ushort(__float2bfloat16_rn(r[3] - __bfloat162float(hb)));
        *(ushort4*)(chi + o + c * 4) = uh;
        *(ushort4*)(clo + o + c * 4) = ul;
    }
}

// ================= launch =======================================================
extern "C" void kernel_launch(void* const* d_in, const int* in_sizes, int n_in,
                              void* d_out, int out_size)
{
    const float* q  = (const float*)d_in[0];
    const float* k  = (const float*)d_in[1];
    const float* v  = (const float*)d_in[2];
    const float* Wq = (const float*)d_in[3];
    const float* bq = (const float*)d_in[4];
    const float* Wk = (const float*)d_in[5];
    const float* bk = (const float*)d_in[6];
    const float* Wv = (const float*)d_in[7];
    const float* bv = (const float*)d_in[8];
    const float* Wo = (const float*)d_in[9];
    const float* bo = (const float*)d_in[10];
    float* out = (float*)d_out;

    float *pQ, *pK, *pV;
    __nv_bfloat16 *pAhi, *pAlo, *pWhi, *pWlo;
    cudaGetSymbolAddress((void**)&pQ,   g_Q);
    cudaGetSymbolAddress((void**)&pK,   g_K);
    cudaGetSymbolAddress((void**)&pV,   g_V);
    cudaGetSymbolAddress((void**)&pAhi, g_ahi);
    cudaGetSymbolAddress((void**)&pAlo, g_alo);
    cudaGetSymbolAddress((void**)&pWhi, g_wthi);
    cudaGetSymbolAddress((void**)&pWlo, g_wtlo);

    cudaFuncSetAttribute(gemm_mma, cudaFuncAttributeMaxDynamicSharedMemorySize, GEMM_SMEM);

    // weight transpose + bf16 split (also zeroes g_vsum)
    WIn win; win.W[0] = Wq; win.W[1] = Wk; win.W[2] = Wv; win.W[3] = Wo;
    wt_all<<<dim3(DM / 32, DM / 32, 4), dim3(32, 8)>>>(win, pWhi, pWlo);

    const int CVB = 256, CVG = (TOK * DM / 4) / CVB;

    // convert q,k,v in one launch
    CIn cin; cin.x[0] = q; cin.x[1] = k; cin.x[2] = v;
    conv_act<<<dim3(CVG, 3), CVB>>>(cin, pAhi, pAlo);

    // Q,K,V projections in one batched launch; V (z=2) fuses column-sum
    GOut g3;
    g3.C[0] = pQ;  g3.C[1] = pK;  g3.C[2] = pV;
    g3.bias[0] = bq; g3.bias[1] = bk; g3.bias[2] = bv;
    gemm_mma<<<dim3(DM / 128, TOK / 128, 3), 256, GEMM_SMEM>>>(pAhi, pAlo, pWhi, pWlo, g3, 2);

    // attention -> ctx written as bf16 hi/lo into activation slot 0
    // 64 rows per block: 32768 rows / 64 = 512 blocks
    attn_kernel<<<512, 256>>>(pQ, pK, pV, pAhi, pAlo);

    // out = ctx@Wo+bo
    GOut g1;
    g1.C[0] = out; g1.C[1] = out; g1.C[2] = out;
    g1.bias[0] = bo; g1.bias[1] = bo; g1.bias[2] = bo;
    gemm_mma<<<dim3(DM / 128, TOK / 128, 1), 256, GEMM_SMEM>>>(
        pAhi, pAlo, pWhi + 3 * (size_t)DM * DM, pWlo + 3 * (size_t)DM * DM, g1, -1);
}

// round 11
// speedup vs baseline: 1.1050x; 1.1050x over previous
#include <cuda_runtime.h>
#include <cuda_bf16.h>
#include <math.h>
#include <stdint.h>

// Problem constants: bs=2, seq=2048, d_model=512, heads=8, d_k=64
#define DM     512
#define HEADS  8
#define DK     64
#define SEQ    2048
#define BS     2
#define TOK    (SEQ*BS)     // 4096

// ---------------- scratch (device globals; no allocations allowed) -------------
__device__ float g_Q[TOK * DM];
__device__ float g_K[TOK * DM];
__device__ float g_V[TOK * DM];
__device__ __nv_bfloat16 g_ahi[3 * TOK * DM];
__device__ __nv_bfloat16 g_alo[3 * TOK * DM];
__device__ __nv_bfloat16 g_wthi[4][DM * DM];   // transposed weights [N,K], hi part
__device__ __nv_bfloat16 g_wtlo[4][DM * DM];   // lo part
__device__ float g_vsum[BS * DM];

struct WIn  { const float* W[4]; };
struct CIn  { const float* x[3]; };
struct GOut { float* C[3]; const float* bias[3]; };

// ================= helpers ======================================================
__device__ __forceinline__ uint32_t smem_u32(const void* p) {
    uint32_t a;
    asm("{ .reg .u64 t; cvta.to.shared.u64 t, %1; cvt.u32.u64 %0, t; }" : "=r"(a) : "l"(p));
    return a;
}
__device__ __forceinline__ uint32_t sw128(uint32_t o) { return o ^ ((o >> 3) & 0x70); }

__device__ __forceinline__ void cp16(uint32_t dst, const void* src) {
    asm volatile("cp.async.cg.shared.global [%0], [%1], 16;" :: "r"(dst), "l"(src));
}
__device__ __forceinline__ void ldsm4(uint32_t* r, uint32_t addr) {
    asm volatile("ldmatrix.sync.aligned.m8n8.x4.shared.b16 {%0,%1,%2,%3}, [%4];"
        : "=r"(r[0]), "=r"(r[1]), "=r"(r[2]), "=r"(r[3]) : "r"(addr));
}
__device__ __forceinline__ void mma16816(float* c, const uint32_t* a, uint32_t b0, uint32_t b1) {
    asm volatile("mma.sync.aligned.m16n8k16.row.col.f32.bf16.bf16.f32 "
        "{%0,%1,%2,%3}, {%4,%5,%6,%7}, {%8,%9}, {%0,%1,%2,%3};"
        : "+f"(c[0]), "+f"(c[1]), "+f"(c[2]), "+f"(c[3])
        : "r"(a[0]), "r"(a[1]), "r"(a[2]), "r"(a[3]), "r"(b0), "r"(b1));
}

// ================= bf16-split mma.sync GEMM (round-8 proven) ====================
#define KC      64
#define NKC     (DM / KC)               // 8
#define TILE_B  (128 * 128)             // 16 KB per array per stage
#define STG_B   (4 * TILE_B)            // 64 KB per stage
#define GEMM_SMEM (2 * STG_B)           // 131072

__global__ void __launch_bounds__(256, 1)
gemm_mma(const __nv_bfloat16* __restrict__ Ahi_base, const __nv_bfloat16* __restrict__ Alo_base,
         const __nv_bfloat16* __restrict__ Whi_base, const __nv_bfloat16* __restrict__ Wlo_base,
         GOut outs, int vsum_z)
{
    extern __shared__ char smem[];
    const uint32_t sb = smem_u32(smem);
    const int tid  = threadIdx.x;
    const int wid  = tid >> 5;
    const int lane = tid & 31;
    const int m0   = blockIdx.y * 128;
    const int n0   = blockIdx.x * 128;
    const int z    = blockIdx.z;

    const __nv_bfloat16* arrs[4] = {
        Ahi_base + (size_t)z * TOK * DM, Alo_base + (size_t)z * TOK * DM,
        Whi_base + (size_t)z * DM * DM,  Wlo_base + (size_t)z * DM * DM };
    float* C = outs.C[z];
    const float* bias = outs.bias[z];

    const int lrow = tid >> 1;
    const int lc0  = (tid & 1) * 4;

    auto load_stage = [&](int kc, int s) {
        const uint32_t stg = sb + s * STG_B;
        #pragma unroll
        for (int a = 0; a < 4; a++) {
            const int grow = ((a < 2) ? m0 : n0) + lrow;
            const __nv_bfloat16* src = arrs[a] + (size_t)grow * DM + kc * KC + lc0 * 8;
            const uint32_t abase = stg + a * TILE_B;
            #pragma unroll
            for (int c = 0; c < 4; c++)
                cp16(abase + sw128(lrow * 128 + (lc0 + c) * 16), src + c * 8);
        }
        asm volatile("cp.async.commit_group;" ::: "memory");
    };

    load_stage(0, 0);
    load_stage(1, 1);

    const int wm = (wid & 1) * 64;
    const int wn = (wid >> 1) * 32;
    const int lane8 = lane & 7;
    const int rowp8 = ((lane >> 3) & 1) * 8;
    const int kp1   = (lane >> 4) & 1;

    float acc[4][4][4];
    #pragma unroll
    for (int f = 0; f < 4; f++)
        #pragma unroll
        for (int n = 0; n < 4; n++)
            #pragma unroll
            for (int e = 0; e < 4; e++) acc[f][n][e] = 0.f;

    for (int kc = 0; kc < NKC; kc++) {
        const int s = kc & 1;
        if (kc < NKC - 1) asm volatile("cp.async.wait_group 1;" ::: "memory");
        else              asm volatile("cp.async.wait_group 0;" ::: "memory");
        __syncthreads();

        const uint32_t sAh = sb + s * STG_B + 0 * TILE_B;
        const uint32_t sAl = sb + s * STG_B + 1 * TILE_B;
        const uint32_t sBh = sb + s * STG_B + 2 * TILE_B;
        const uint32_t sBl = sb + s * STG_B + 3 * TILE_B;

        #pragma unroll
        for (int kk = 0; kk < KC / 16; kk++) {
            const int ch = kk * 2 + kp1;
            uint32_t bh[2][4], bl[2][4];
            #pragma unroll
            for (int p = 0; p < 2; p++) {
                const uint32_t off = sw128((wn + p * 16 + lane8 + rowp8) * 128 + ch * 16);
                ldsm4(bh[p], sBh + off);
                ldsm4(bl[p], sBl + off);
            }
            uint32_t ah[4][4], al[4][4];
            #pragma unroll
            for (int f = 0; f < 4; f++) {
                const uint32_t off = sw128((wm + f * 16 + lane8 + rowp8) * 128 + ch * 16);
                ldsm4(ah[f], sAh + off);
                ldsm4(al[f], sAl + off);
            }
            #pragma unroll
            for (int f = 0; f < 4; f++) {
                #pragma unroll
                for (int p = 0; p < 2; p++) {
                    mma16816(acc[f][2 * p + 0], ah[f], bh[p][0], bh[p][2]);
                    mma16816(acc[f][2 * p + 1], ah[f], bh[p][1], bh[p][3]);
                    mma16816(acc[f][2 * p + 0], ah[f], bl[p][0], bl[p][2]);
                    mma16816(acc[f][2 * p + 1], ah[f], bl[p][1], bl[p][3]);
                    mma16816(acc[f][2 * p + 0], al[f], bh[p][0], bh[p][2]);
                    mma16816(acc[f][2 * p + 1], al[f], bh[p][1], bh[p][3]);
                }
            }
        }
        __syncthreads();
        if (kc + 2 < NKC) load_stage(kc + 2, s);
    }

    const int row0 = m0 + wm + (lane >> 2);
    const int colb = n0 + wn + (lane & 3) * 2;
    float cs0[4], cs1[4];
    #pragma unroll
    for (int n = 0; n < 4; n++) { cs0[n] = 0.f; cs1[n] = 0.f; }

    #pragma unroll
    for (int f = 0; f < 4; f++) {
        #pragma unroll
        for (int n = 0; n < 4; n++) {
            const int col = colb + n * 8;
            const float2 bv = *(const float2*)(bias + col);
            float2 o0, o1;
            o0.x = acc[f][n][0] + bv.x; o0.y = acc[f][n][1] + bv.y;
            o1.x = acc[f][n][2] + bv.x; o1.y = acc[f][n][3] + bv.y;
            cs0[n] += o0.x + o1.x;
            cs1[n] += o0.y + o1.y;
            *(float2*)(C + (size_t)(row0 + f * 16 + 0) * DM + col) = o0;
            *(float2*)(C + (size_t)(row0 + f * 16 + 8) * DM + col) = o1;
        }
    }

    if (z == vsum_z) {
        #pragma unroll
        for (int n = 0; n < 4; n++) {
            #pragma unroll
            for (int o = 4; o <= 16; o <<= 1) {
                cs0[n] += __shfl_xor_sync(0xffffffffu, cs0[n], o);
                cs1[n] += __shfl_xor_sync(0xffffffffu, cs1[n], o);
            }
        }
        if (lane < 4) {
            const int b = m0 / SEQ;
            #pragma unroll
            for (int n = 0; n < 4; n++) {
                const int col = n0 + wn + (lane & 3) * 2 + n * 8;
                atomicAdd(&g_vsum[b * DM + col + 0], cs0[n]);
                atomicAdd(&g_vsum[b * DM + col + 1], cs1[n]);
            }
        }
    }
}

// ================= conversion kernels ==========================================
__global__ void conv_act(CIn in, __nv_bfloat16* __restrict__ hi, __nv_bfloat16* __restrict__ lo)
{
    const int z = blockIdx.y;
    const size_t i = (size_t)blockIdx.x * blockDim.x + threadIdx.x;
    const size_t o = (size_t)z * (TOK * DM / 4) + i;
    float4 v = ((const float4*)in.x[z])[i];
    __nv_bfloat16 h[4], l[4];
    float f[4] = { v.x, v.y, v.z, v.w };
    #pragma unroll
    for (int t = 0; t < 4; t++) {
        h[t] = __float2bfloat16_rn(f[t]);
        l[t] = __float2bfloat16_rn(f[t] - __bfloat162float(h[t]));
    }
    ((ushort4*)hi)[o] = make_ushort4(__bfloat16_as_ushort(h[0]), __bfloat16_as_ushort(h[1]),
                                     __bfloat16_as_ushort(h[2]), __bfloat16_as_ushort(h[3]));
    ((ushort4*)lo)[o] = make_ushort4(__bfloat16_as_ushort(l[0]), __bfloat16_as_ushort(l[1]),
                                     __bfloat16_as_ushort(l[2]), __bfloat16_as_ushort(l[3]));
}

__global__ void wt_all(WIn in, __nv_bfloat16* __restrict__ hi, __nv_bfloat16* __restrict__ lo)
{
    __shared__ float t[32][33];
    const int z = blockIdx.z;
    const float* W = in.W[z];
    __nv_bfloat16* ho = hi + (size_t)z * DM * DM;
    __nv_bfloat16* lo2 = lo + (size_t)z * DM * DM;
    const int bx = blockIdx.x * 32;   // n
    const int by = blockIdx.y * 32;   // k
    const int x = threadIdx.x, y = threadIdx.y;
    const int tid = y * 32 + x;

    if (z == 0 && blockIdx.x == 0 && blockIdx.y == 0) {
        #pragma unroll
        for (int r = 0; r < BS * DM / 256; r++) g_vsum[tid + r * 256] = 0.f;
    }

    #pragma unroll
    for (int r = y; r < 32; r += 8)
        t[r][x] = W[(size_t)(by + r) * DM + bx + x];
    __syncthreads();
    #pragma unroll
    for (int i = y; i < 32; i += 8) {
        float v = t[x][i];
        __nv_bfloat16 h = __float2bfloat16_rn(v);
        __nv_bfloat16 l = __float2bfloat16_rn(v - __bfloat162float(h));
        size_t o = (size_t)(bx + i) * DM + by + x;
        ho[o] = h;
        lo2[o] = l;
    }
}

// ================= banded attention (closed-form full-row softmax) ==============
// 8 lanes per row (8 dims/lane), 4 rows per warp. Interior fast path with
// C = 5 - |delta|; edge warps take the generic clamped path.
__global__ __launch_bounds__(256)
void attn_kernel(const float* __restrict__ Q, const float* __restrict__ K,
                 const float* __restrict__ V,
                 __nv_bfloat16* __restrict__ chi, __nv_bfloat16* __restrict__ clo)
{
    const int lane = threadIdx.x & 31;
    const int wid  = threadIdx.x >> 5;
    const int sub  = lane >> 3;          // row within warp (0..3)
    const int sl   = lane & 7;           // dim slice (0..7), 8 floats each

    const int row_id = (blockIdx.x * 8 + wid) * 4 + sub;
    const int i  = row_id & (SEQ - 1);
    const int bh = row_id >> 11;         // SEQ = 2^11
    const int h  = bh & (HEADS - 1);
    const int b  = bh >> 3;

    const size_t base = ((size_t)b * SEQ) * DM + h * DK + sl * 8;
    const float* qp = Q + base + (size_t)i * DM;
    const float4 q0 = *(const float4*)qp;
    const float4 q1 = *(const float4*)(qp + 4);

    float s[9];
    float smax = 0.f;   // implicit zeros outside band participate in the max
    int jlo, nb;

    const bool interior = (i >= 4) && (i <= SEQ - 5);
    if (__all_sync(0xffffffffu, interior)) {
        jlo = i - 4; nb = 9;
        const float* kp = K + base + (size_t)jlo * DM;
        #pragma unroll
        for (int t = 0; t < 9; t++) {
            const float4 k0 = *(const float4*)kp;
            const float4 k1 = *(const float4*)(kp + 4);
            kp += DM;
            float p = q0.x * k0.x + q0.y * k0.y + q0.z * k0.z + q0.w * k0.w
                    + q1.x * k1.x + q1.y * k1.y + q1.z * k1.z + q1.w * k1.w;
            p += __shfl_xor_sync(0xffffffffu, p, 1);
            p += __shfl_xor_sync(0xffffffffu, p, 2);
            p += __shfl_xor_sync(0xffffffffu, p, 4);
            const float cc = (float)(5 - ((t > 4) ? (t - 4) : (4 - t)));
            s[t] = p * 0.125f * cc;
            smax = fmaxf(smax, s[t]);
        }
    } else {
        jlo = max(i - 4, 0);
        const int jhi = min(i + 4, SEQ - 1);
        nb = jhi - jlo + 1;
        #pragma unroll
        for (int t = 0; t < 9; t++) {
            const int j = jlo + t;
            const bool valid = (j <= jhi);
            const int jc = valid ? j : jhi;
            const float* kp = K + base + (size_t)jc * DM;
            const float4 k0 = *(const float4*)kp;
            const float4 k1 = *(const float4*)(kp + 4);
            float p = q0.x * k0.x + q0.y * k0.y + q0.z * k0.z + q0.w * k0.w
                    + q1.x * k1.x + q1.y * k1.y + q1.z * k1.z + q1.w * k1.w;
            p += __shfl_xor_sync(0xffffffffu, p, 1);
            p += __shfl_xor_sync(0xffffffffu, p, 2);
            p += __shfl_xor_sync(0xffffffffu, p, 4);
            const int mn = min(i, j), mx = max(i, j);
            const int clo2 = max(mx - 2, 0);
            const int chi2 = min(mn + 2, SEQ - 1);
            const float cc = (float)(chi2 - clo2 + 1);
            s[t] = valid ? p * 0.125f * cc : -1e30f;
            smax = fmaxf(smax, s[t]);
        }
    }

    const float w0 = __expf(-smax);
    float Z = (float)(SEQ - nb) * w0;
    float w[9];
    #pragma unroll
    for (int t = 0; t < 9; t++) { w[t] = __expf(s[t] - smax); Z += w[t]; }
    const float rZ = 1.f / Z;

    float4 a0, a1;
    a0.x = a0.y = a0.z = a0.w = 0.f;
    a1.x = a1.y = a1.z = a1.w = 0.f;
    {
        const float* vp = V + base + (size_t)jlo * DM;
        #pragma unroll
        for (int t = 0; t < 9; t++) {
            const float wt = (t < nb) ? (w[t] - w0) : 0.f;
            const float4 v0 = *(const float4*)vp;
            const float4 v1 = *(const float4*)(vp + 4);
            if (t < nb - 1) vp += DM;   // stay in bounds for tail
            a0.x += wt * v0.x; a0.y += wt * v0.y; a0.z += wt * v0.z; a0.w += wt * v0.w;
            a1.x += wt * v1.x; a1.y += wt * v1.y; a1.z += wt * v1.z; a1.w += wt * v1.w;
        }
    }

    const float* vsp = g_vsum + b * DM + h * DK + sl * 8;
    const float4 vs0 = *(const float4*)vsp;
    const float4 vs1 = *(const float4*)(vsp + 4);
    float r[8];
    r[0] = (a0.x + w0 * vs0.x) * rZ;
    r[1] = (a0.y + w0 * vs0.y) * rZ;
    r[2] = (a0.z + w0 * vs0.z) * rZ;
    r[3] = (a0.w + w0 * vs0.w) * rZ;
    r[4] = (a1.x + w0 * vs1.x) * rZ;
    r[5] = (a1.y + w0 * vs1.y) * rZ;
    r[6] = (a1.z + w0 * vs1.z) * rZ;
    r[7] = (a1.w + w0 * vs1.w) * rZ;

    ushort hbits[8], lbits[8];
    #pragma unroll
    for (int c = 0; c < 8; c++) {
        const __nv_bfloat16 hb = __float2bfloat16_rn(r[c]);
        hbits[c] = __bfloat16_as_ushort(hb);
        lbits[c] = __bfloat16_as_ushort(__float2bfloat16_rn(r[c] - __bfloat162float(hb)));
    }
    const size_t o = base + (size_t)i * DM;
    uint4 uh, ul;
    uh.x = (uint32_t)hbits[0] | ((uint32_t)hbits[1] << 16);
    uh.y = (uint32_t)hbits[2] | ((uint32_t)hbits[3] << 16);
    uh.z = (uint32_t)hbits[4] | ((uint32_t)hbits[5] << 16);
    uh.w = (uint32_t)hbits[6] | ((uint32_t)hbits[7] << 16);
    ul.x = (uint32_t)lbits[0] | ((uint32_t)lbits[1] << 16);
    ul.y = (uint32_t)lbits[2] | ((uint32_t)lbits[3] << 16);
    ul.z = (uint32_t)lbits[4] | ((uint32_t)lbits[5] << 16);
    ul.w = (uint32_t)lbits[6] | ((uint32_t)lbits[7] << 16);
    *(uint4*)(chi + o) = uh;
    *(uint4*)(clo + o) = ul;
}

// ================= launch =======================================================
extern "C" void kernel_launch(void* const* d_in, const int* in_sizes, int n_in,
                              void* d_out, int out_size)
{
    const float* q  = (const float*)d_in[0];
    const float* k  = (const float*)d_in[1];
    const float* v  = (const float*)d_in[2];
    const float* Wq = (const float*)d_in[3];
    const float* bq = (const float*)d_in[4];
    const float* Wk = (const float*)d_in[5];
    const float* bk = (const float*)d_in[6];
    const float* Wv = (const float*)d_in[7];
    const float* bv = (const float*)d_in[8];
    const float* Wo = (const float*)d_in[9];
    const float* bo = (const float*)d_in[10];
    float* out = (float*)d_out;

    float *pQ, *pK, *pV;
    __nv_bfloat16 *pAhi, *pAlo, *pWhi, *pWlo;
    cudaGetSymbolAddress((void**)&pQ,   g_Q);
    cudaGetSymbolAddress((void**)&pK,   g_K);
    cudaGetSymbolAddress((void**)&pV,   g_V);
    cudaGetSymbolAddress((void**)&pAhi, g_ahi);
    cudaGetSymbolAddress((void**)&pAlo, g_alo);
    cudaGetSymbolAddress((void**)&pWhi, g_wthi);
    cudaGetSymbolAddress((void**)&pWlo, g_wtlo);

    cudaFuncSetAttribute(gemm_mma, cudaFuncAttributeMaxDynamicSharedMemorySize, GEMM_SMEM);

    // weight transpose + bf16 split (also zeroes g_vsum)
    WIn win; win.W[0] = Wq; win.W[1] = Wk; win.W[2] = Wv; win.W[3] = Wo;
    wt_all<<<dim3(DM / 32, DM / 32, 4), dim3(32, 8)>>>(win, pWhi, pWlo);

    const int CVB = 256, CVG = (TOK * DM / 4) / CVB;

    // convert q,k,v in one launch
    CIn cin; cin.x[0] = q; cin.x[1] = k; cin.x[2] = v;
    conv_act<<<dim3(CVG, 3), CVB>>>(cin, pAhi, pAlo);

    // Q,K,V projections in one batched launch; V (z=2) fuses column-sum
    GOut g3;
    g3.C[0] = pQ;  g3.C[1] = pK;  g3.C[2] = pV;
    g3.bias[0] = bq; g3.bias[1] = bk; g3.bias[2] = bv;
    gemm_mma<<<dim3(DM / 128, TOK / 128, 3), 256, GEMM_SMEM>>>(pAhi, pAlo, pWhi, pWlo, g3, 2);

    // attention -> ctx written as bf16 hi/lo into activation slot 0
    // 32 rows per block: 32768 rows / 32 = 1024 blocks
    attn_kernel<<<1024, 256>>>(pQ, pK, pV, pAhi, pAlo);

    // out = ctx@Wo+bo
    GOut g1;
    g1.C[0] = out; g1.C[1] = out; g1.C[2] = out;
    g1.bias[0] = bo; g1.bias[1] = bo; g1.bias[2] = bo;
    gemm_mma<<<dim3(DM / 128, TOK / 128, 1), 256, GEMM_SMEM>>>(
        pAhi, pAlo, pWhi + 3 * (size_t)DM * DM, pWlo + 3 * (size_t)DM * DM, g1, -1);
}

// round 13
// speedup vs baseline: 1.1098x; 1.0043x over previous
#include <cuda_runtime.h>
#include <cuda_bf16.h>
#include <math.h>
#include <stdint.h>

// Problem constants: bs=2, seq=2048, d_model=512, heads=8, d_k=64
#define DM     512
#define HEADS  8
#define DK     64
#define SEQ    2048
#define BS     2
#define TOK    (SEQ*BS)     // 4096

// ---------------- scratch (device globals; no allocations allowed) -------------
__device__ float g_Q[TOK * DM];
__device__ float g_K[TOK * DM];
__device__ float g_V[TOK * DM];
__device__ __nv_bfloat16 g_ahi[3 * TOK * DM];
__device__ __nv_bfloat16 g_alo[3 * TOK * DM];
__device__ __nv_bfloat16 g_wthi[4][DM * DM];   // transposed weights [N,K], hi part
__device__ __nv_bfloat16 g_wtlo[4][DM * DM];   // lo part
__device__ float g_vsum[BS * DM];

struct WIn  { const float* W[4]; };
struct CIn  { const float* x[3]; };
struct GOut { float* C[3]; const float* bias[3]; };

// ================= helpers ======================================================
__device__ __forceinline__ uint32_t smem_u32(const void* p) {
    uint32_t a;
    asm("{ .reg .u64 t; cvta.to.shared.u64 t, %1; cvt.u32.u64 %0, t; }" : "=r"(a) : "l"(p));
    return a;
}
__device__ __forceinline__ uint32_t sw128(uint32_t o) { return o ^ ((o >> 3) & 0x70); }

__device__ __forceinline__ void cp16(uint32_t dst, const void* src) {
    asm volatile("cp.async.cg.shared.global [%0], [%1], 16;" :: "r"(dst), "l"(src));
}
__device__ __forceinline__ void ldsm4(uint32_t* r, uint32_t addr) {
    asm volatile("ldmatrix.sync.aligned.m8n8.x4.shared.b16 {%0,%1,%2,%3}, [%4];"
        : "=r"(r[0]), "=r"(r[1]), "=r"(r[2]), "=r"(r[3]) : "r"(addr));
}
__device__ __forceinline__ void mma16816(float* c, const uint32_t* a, uint32_t b0, uint32_t b1) {
    asm volatile("mma.sync.aligned.m16n8k16.row.col.f32.bf16.bf16.f32 "
        "{%0,%1,%2,%3}, {%4,%5,%6,%7}, {%8,%9}, {%0,%1,%2,%3};"
        : "+f"(c[0]), "+f"(c[1]), "+f"(c[2]), "+f"(c[3])
        : "r"(a[0]), "r"(a[1]), "r"(a[2]), "r"(a[3]), "r"(b0), "r"(b1));
}

// ================= bf16-split mma.sync GEMM ====================================
// Three-pass MMA schedule: same-accumulator reuse distance 32 MMAs (was 2),
// hiding HMMA latency with only 2 warps/SMSP.
#define KC      64
#define NKC     (DM / KC)               // 8
#define TILE_B  (128 * 128)             // 16 KB per array per stage
#define STG_B   (4 * TILE_B)            // 64 KB per stage
#define GEMM_SMEM (2 * STG_B)           // 131072

__global__ void __launch_bounds__(256, 1)
gemm_mma(const __nv_bfloat16* __restrict__ Ahi_base, const __nv_bfloat16* __restrict__ Alo_base,
         const __nv_bfloat16* __restrict__ Whi_base, const __nv_bfloat16* __restrict__ Wlo_base,
         GOut outs, int vsum_z)
{
    extern __shared__ char smem[];
    const uint32_t sb = smem_u32(smem);
    const int tid  = threadIdx.x;
    const int wid  = tid >> 5;
    const int lane = tid & 31;
    const int m0   = blockIdx.y * 128;
    const int n0   = blockIdx.x * 128;
    const int z    = blockIdx.z;

    const __nv_bfloat16* arrs[4] = {
        Ahi_base + (size_t)z * TOK * DM, Alo_base + (size_t)z * TOK * DM,
        Whi_base + (size_t)z * DM * DM,  Wlo_base + (size_t)z * DM * DM };
    float* C = outs.C[z];
    const float* bias = outs.bias[z];

    const int lrow = tid >> 1;
    const int lc0  = (tid & 1) * 4;

    auto load_stage = [&](int kc, int s) {
        const uint32_t stg = sb + s * STG_B;
        #pragma unroll
        for (int a = 0; a < 4; a++) {
            const int grow = ((a < 2) ? m0 : n0) + lrow;
            const __nv_bfloat16* src = arrs[a] + (size_t)grow * DM + kc * KC + lc0 * 8;
            const uint32_t abase = stg + a * TILE_B;
            #pragma unroll
            for (int c = 0; c < 4; c++)
                cp16(abase + sw128(lrow * 128 + (lc0 + c) * 16), src + c * 8);
        }
        asm volatile("cp.async.commit_group;" ::: "memory");
    };

    load_stage(0, 0);
    load_stage(1, 1);

    const int wm = (wid & 1) * 64;
    const int wn = (wid >> 1) * 32;
    const int lane8 = lane & 7;
    const int rowp8 = ((lane >> 3) & 1) * 8;
    const int kp1   = (lane >> 4) & 1;

    float acc[4][4][4];
    #pragma unroll
    for (int f = 0; f < 4; f++)
        #pragma unroll
        for (int n = 0; n < 4; n++)
            #pragma unroll
            for (int e = 0; e < 4; e++) acc[f][n][e] = 0.f;

    for (int kc = 0; kc < NKC; kc++) {
        const int s = kc & 1;
        if (kc < NKC - 1) asm volatile("cp.async.wait_group 1;" ::: "memory");
        else              asm volatile("cp.async.wait_group 0;" ::: "memory");
        __syncthreads();

        const uint32_t sAh = sb + s * STG_B + 0 * TILE_B;
        const uint32_t sAl = sb + s * STG_B + 1 * TILE_B;
        const uint32_t sBh = sb + s * STG_B + 2 * TILE_B;
        const uint32_t sBl = sb + s * STG_B + 3 * TILE_B;

        #pragma unroll
        for (int kk = 0; kk < KC / 16; kk++) {
            const int ch = kk * 2 + kp1;
            uint32_t bh[2][4], bl[2][4];
            #pragma unroll
            for (int p = 0; p < 2; p++) {
                const uint32_t off = sw128((wn + p * 16 + lane8 + rowp8) * 128 + ch * 16);
                ldsm4(bh[p], sBh + off);
                ldsm4(bl[p], sBl + off);
            }
            uint32_t ah[4][4], al[4][4];
            #pragma unroll
            for (int f = 0; f < 4; f++) {
                const uint32_t off = sw128((wm + f * 16 + lane8 + rowp8) * 128 + ch * 16);
                ldsm4(ah[f], sAh + off);
                ldsm4(al[f], sAl + off);
            }
            // Pass 1: Ahi x Bhi — 16 independent accumulator tiles
            #pragma unroll
            for (int f = 0; f < 4; f++)
                #pragma unroll
                for (int p = 0; p < 2; p++) {
                    mma16816(acc[f][2 * p + 0], ah[f], bh[p][0], bh[p][2]);
                    mma16816(acc[f][2 * p + 1], ah[f], bh[p][1], bh[p][3]);
                }
            // Pass 2: Ahi x Blo
            #pragma unroll
            for (int f = 0; f < 4; f++)
                #pragma unroll
                for (int p = 0; p < 2; p++) {
                    mma16816(acc[f][2 * p + 0], ah[f], bl[p][0], bl[p][2]);
                    mma16816(acc[f][2 * p + 1], ah[f], bl[p][1], bl[p][3]);
                }
            // Pass 3: Alo x Bhi
            #pragma unroll
            for (int f = 0; f < 4; f++)
                #pragma unroll
                for (int p = 0; p < 2; p++) {
                    mma16816(acc[f][2 * p + 0], al[f], bh[p][0], bh[p][2]);
                    mma16816(acc[f][2 * p + 1], al[f], bh[p][1], bh[p][3]);
                }
        }
        __syncthreads();
        if (kc + 2 < NKC) load_stage(kc + 2, s);
    }

    const int row0 = m0 + wm + (lane >> 2);
    const int colb = n0 + wn + (lane & 3) * 2;
    float cs0[4], cs1[4];
    #pragma unroll
    for (int n = 0; n < 4; n++) { cs0[n] = 0.f; cs1[n] = 0.f; }

    #pragma unroll
    for (int f = 0; f < 4; f++) {
        #pragma unroll
        for (int n = 0; n < 4; n++) {
            const int col = colb + n * 8;
            const float2 bv = *(const float2*)(bias + col);
            float2 o0, o1;
            o0.x = acc[f][n][0] + bv.x; o0.y = acc[f][n][1] + bv.y;
            o1.x = acc[f][n][2] + bv.x; o1.y = acc[f][n][3] + bv.y;
            cs0[n] += o0.x + o1.x;
            cs1[n] += o0.y + o1.y;
            *(float2*)(C + (size_t)(row0 + f * 16 + 0) * DM + col) = o0;
            *(float2*)(C + (size_t)(row0 + f * 16 + 8) * DM + col) = o1;
        }
    }

    if (z == vsum_z) {
        #pragma unroll
        for (int n = 0; n < 4; n++) {
            #pragma unroll
            for (int o = 4; o <= 16; o <<= 1) {
                cs0[n] += __shfl_xor_sync(0xffffffffu, cs0[n], o);
                cs1[n] += __shfl_xor_sync(0xffffffffu, cs1[n], o);
            }
        }
        if (lane < 4) {
            const int b = m0 / SEQ;
            #pragma unroll
            for (int n = 0; n < 4; n++) {
                const int col = n0 + wn + (lane & 3) * 2 + n * 8;
                atomicAdd(&g_vsum[b * DM + col + 0], cs0[n]);
                atomicAdd(&g_vsum[b * DM + col + 1], cs1[n]);
            }
        }
    }
}

// ================= conversion kernels ==========================================
__global__ void conv_act(CIn in, __nv_bfloat16* __restrict__ hi, __nv_bfloat16* __restrict__ lo)
{
    const int z = blockIdx.y;
    const size_t i = (size_t)blockIdx.x * blockDim.x + threadIdx.x;
    const size_t o = (size_t)z * (TOK * DM / 4) + i;
    float4 v = ((const float4*)in.x[z])[i];
    __nv_bfloat16 h[4], l[4];
    float f[4] = { v.x, v.y, v.z, v.w };
    #pragma unroll
    for (int t = 0; t < 4; t++) {
        h[t] = __float2bfloat16_rn(f[t]);
        l[t] = __float2bfloat16_rn(f[t] - __bfloat162float(h[t]));
    }
    ((ushort4*)hi)[o] = make_ushort4(__bfloat16_as_ushort(h[0]), __bfloat16_as_ushort(h[1]),
                                     __bfloat16_as_ushort(h[2]), __bfloat16_as_ushort(h[3]));
    ((ushort4*)lo)[o] = make_ushort4(__bfloat16_as_ushort(l[0]), __bfloat16_as_ushort(l[1]),
                                     __bfloat16_as_ushort(l[2]), __bfloat16_as_ushort(l[3]));
}

__global__ void wt_all(WIn in, __nv_bfloat16* __restrict__ hi, __nv_bfloat16* __restrict__ lo)
{
    __shared__ float t[32][33];
    const int z = blockIdx.z;
    const float* W = in.W[z];
    __nv_bfloat16* ho = hi + (size_t)z * DM * DM;
    __nv_bfloat16* lo2 = lo + (size_t)z * DM * DM;
    const int bx = blockIdx.x * 32;   // n
    const int by = blockIdx.y * 32;   // k
    const int x = threadIdx.x, y = threadIdx.y;
    const int tid = y * 32 + x;

    if (z == 0 && blockIdx.x == 0 && blockIdx.y == 0) {
        #pragma unroll
        for (int r = 0; r < BS * DM / 256; r++) g_vsum[tid + r * 256] = 0.f;
    }

    #pragma unroll
    for (int r = y; r < 32; r += 8)
        t[r][x] = W[(size_t)(by + r) * DM + bx + x];
    __syncthreads();
    #pragma unroll
    for (int i = y; i < 32; i += 8) {
        float v = t[x][i];
        __nv_bfloat16 h = __float2bfloat16_rn(v);
        __nv_bfloat16 l = __float2bfloat16_rn(v - __bfloat162float(h));
        size_t o = (size_t)(bx + i) * DM + by + x;
        ho[o] = h;
        lo2[o] = l;
    }
}

// ================= banded attention (closed-form full-row softmax) ==============
// 8 lanes per row (8 dims/lane), 4 rows per warp. Interior fast path with
// C = 5 - |delta|; edge warps take the generic clamped path.
__global__ __launch_bounds__(256)
void attn_kernel(const float* __restrict__ Q, const float* __restrict__ K,
                 const float* __restrict__ V,
                 __nv_bfloat16* __restrict__ chi, __nv_bfloat16* __restrict__ clo)
{
    const int lane = threadIdx.x & 31;
    const int wid  = threadIdx.x >> 5;
    const int sub  = lane >> 3;          // row within warp (0..3)
    const int sl   = lane & 7;           // dim slice (0..7), 8 floats each

    const int row_id = (blockIdx.x * 8 + wid) * 4 + sub;
    const int i  = row_id & (SEQ - 1);
    const int bh = row_id >> 11;         // SEQ = 2^11
    const int h  = bh & (HEADS - 1);
    const int b  = bh >> 3;

    const size_t base = ((size_t)b * SEQ) * DM + h * DK + sl * 8;
    const float* qp = Q + base + (size_t)i * DM;
    const float4 q0 = *(const float4*)qp;
    const float4 q1 = *(const float4*)(qp + 4);

    float s[9];
    float smax = 0.f;   // implicit zeros outside band participate in the max
    int jlo, nb;

    const bool interior = (i >= 4) && (i <= SEQ - 5);
    if (__all_sync(0xffffffffu, interior)) {
        jlo = i - 4; nb = 9;
        const float* kp = K + base + (size_t)jlo * DM;
        #pragma unroll
        for (int t = 0; t < 9; t++) {
            const float4 k0 = *(const float4*)kp;
            const float4 k1 = *(const float4*)(kp + 4);
            kp += DM;
            float p = q0.x * k0.x + q0.y * k0.y + q0.z * k0.z + q0.w * k0.w
                    + q1.x * k1.x + q1.y * k1.y + q1.z * k1.z + q1.w * k1.w;
            p += __shfl_xor_sync(0xffffffffu, p, 1);
            p += __shfl_xor_sync(0xffffffffu, p, 2);
            p += __shfl_xor_sync(0xffffffffu, p, 4);
            const float cc = (float)(5 - ((t > 4) ? (t - 4) : (4 - t)));
            s[t] = p * 0.125f * cc;
            smax = fmaxf(smax, s[t]);
        }
    } else {
        jlo = max(i - 4, 0);
        const int jhi = min(i + 4, SEQ - 1);
        nb = jhi - jlo + 1;
        #pragma unroll
        for (int t = 0; t < 9; t++) {
            const int j = jlo + t;
            const bool valid = (j <= jhi);
            const int jc = valid ? j : jhi;
            const float* kp = K + base + (size_t)jc * DM;
            const float4 k0 = *(const float4*)kp;
            const float4 k1 = *(const float4*)(kp + 4);
            float p = q0.x * k0.x + q0.y * k0.y + q0.z * k0.z + q0.w * k0.w
                    + q1.x * k1.x + q1.y * k1.y + q1.z * k1.z + q1.w * k1.w;
            p += __shfl_xor_sync(0xffffffffu, p, 1);
            p += __shfl_xor_sync(0xffffffffu, p, 2);
            p += __shfl_xor_sync(0xffffffffu, p, 4);
            const int mn = min(i, j), mx = max(i, j);
            const int clo2 = max(mx - 2, 0);
            const int chi2 = min(mn + 2, SEQ - 1);
            const float cc = (float)(chi2 - clo2 + 1);
            s[t] = valid ? p * 0.125f * cc : -1e30f;
            smax = fmaxf(smax, s[t]);
        }
    }

    const float w0 = __expf(-smax);
    float Z = (float)(SEQ - nb) * w0;
    float w[9];
    #pragma unroll
    for (int t = 0; t < 9; t++) { w[t] = __expf(s[t] - smax); Z += w[t]; }
    const float rZ = 1.f / Z;

    float4 a0, a1;
    a0.x = a0.y = a0.z = a0.w = 0.f;
    a1.x = a1.y = a1.z = a1.w = 0.f;
    {
        const float* vp = V + base + (size_t)jlo * DM;
        #pragma unroll
        for (int t = 0; t < 9; t++) {
            const float wt = (t < nb) ? (w[t] - w0) : 0.f;
            const float4 v0 = *(const float4*)vp;
            const float4 v1 = *(const float4*)(vp + 4);
            if (t < nb - 1) vp += DM;   // stay in bounds for tail
            a0.x += wt * v0.x; a0.y += wt * v0.y; a0.z += wt * v0.z; a0.w += wt * v0.w;
            a1.x += wt * v1.x; a1.y += wt * v1.y; a1.z += wt * v1.z; a1.w += wt * v1.w;
        }
    }

    const float* vsp = g_vsum + b * DM + h * DK + sl * 8;
    const float4 vs0 = *(const float4*)vsp;
    const float4 vs1 = *(const float4*)(vsp + 4);
    float r[8];
    r[0] = (a0.x + w0 * vs0.x) * rZ;
    r[1] = (a0.y + w0 * vs0.y) * rZ;
    r[2] = (a0.z + w0 * vs0.z) * rZ;
    r[3] = (a0.w + w0 * vs0.w) * rZ;
    r[4] = (a1.x + w0 * vs1.x) * rZ;
    r[5] = (a1.y + w0 * vs1.y) * rZ;
    r[6] = (a1.z + w0 * vs1.z) * rZ;
    r[7] = (a1.w + w0 * vs1.w) * rZ;

    ushort hbits[8], lbits[8];
    #pragma unroll
    for (int c = 0; c < 8; c++) {
        const __nv_bfloat16 hb = __float2bfloat16_rn(r[c]);
        hbits[c] = __bfloat16_as_ushort(hb);
        lbits[c] = __bfloat16_as_ushort(__float2bfloat16_rn(r[c] - __bfloat162float(hb)));
    }
    const size_t o = base + (size_t)i * DM;
    uint4 uh, ul;
    uh.x = (uint32_t)hbits[0] | ((uint32_t)hbits[1] << 16);
    uh.y = (uint32_t)hbits[2] | ((uint32_t)hbits[3] << 16);
    uh.z = (uint32_t)hbits[4] | ((uint32_t)hbits[5] << 16);
    uh.w = (uint32_t)hbits[6] | ((uint32_t)hbits[7] << 16);
    ul.x = (uint32_t)lbits[0] | ((uint32_t)lbits[1] << 16);
    ul.y = (uint32_t)lbits[2] | ((uint32_t)lbits[3] << 16);
    ul.z = (uint32_t)lbits[4] | ((uint32_t)lbits[5] << 16);
    ul.w = (uint32_t)lbits[6] | ((uint32_t)lbits[7] << 16);
    *(uint4*)(chi + o) = uh;
    *(uint4*)(clo + o) = ul;
}

// ================= launch =======================================================
extern "C" void kernel_launch(void* const* d_in, const int* in_sizes, int n_in,
                              void* d_out, int out_size)
{
    const float* q  = (const float*)d_in[0];
    const float* k  = (const float*)d_in[1];
    const float* v  = (const float*)d_in[2];
    const float* Wq = (const float*)d_in[3];
    const float* bq = (const float*)d_in[4];
    const float* Wk = (const float*)d_in[5];
    const float* bk = (const float*)d_in[6];
    const float* Wv = (const float*)d_in[7];
    const float* bv = (const float*)d_in[8];
    const float* Wo = (const float*)d_in[9];
    const float* bo = (const float*)d_in[10];
    float* out = (float*)d_out;

    float *pQ, *pK, *pV;
    __nv_bfloat16 *pAhi, *pAlo, *pWhi, *pWlo;
    cudaGetSymbolAddress((void**)&pQ,   g_Q);
    cudaGetSymbolAddress((void**)&pK,   g_K);
    cudaGetSymbolAddress((void**)&pV,   g_V);
    cudaGetSymbolAddress((void**)&pAhi, g_ahi);
    cudaGetSymbolAddress((void**)&pAlo, g_alo);
    cudaGetSymbolAddress((void**)&pWhi, g_wthi);
    cudaGetSymbolAddress((void**)&pWlo, g_wtlo);

    cudaFuncSetAttribute(gemm_mma, cudaFuncAttributeMaxDynamicSharedMemorySize, GEMM_SMEM);

    // weight transpose + bf16 split (also zeroes g_vsum)
    WIn win; win.W[0] = Wq; win.W[1] = Wk; win.W[2] = Wv; win.W[3] = Wo;
    wt_all<<<dim3(DM / 32, DM / 32, 4), dim3(32, 8)>>>(win, pWhi, pWlo);

    const int CVB = 256, CVG = (TOK * DM / 4) / CVB;

    // convert q,k,v in one launch
    CIn cin; cin.x[0] = q; cin.x[1] = k; cin.x[2] = v;
    conv_act<<<dim3(CVG, 3), CVB>>>(cin, pAhi, pAlo);

    // Q,K,V projections in one batched launch; V (z=2) fuses column-sum
    GOut g3;
    g3.C[0] = pQ;  g3.C[1] = pK;  g3.C[2] = pV;
    g3.bias[0] = bq; g3.bias[1] = bk; g3.bias[2] = bv;
    gemm_mma<<<dim3(DM / 128, TOK / 128, 3), 256, GEMM_SMEM>>>(pAhi, pAlo, pWhi, pWlo, g3, 2);

    // attention -> ctx written as bf16 hi/lo into activation slot 0
    attn_kernel<<<1024, 256>>>(pQ, pK, pV, pAhi, pAlo);

    // out = ctx@Wo+bo
    GOut g1;
    g1.C[0] = out; g1.C[1] = out; g1.C[2] = out;
    g1.bias[0] = bo; g1.bias[1] = bo; g1.bias[2] = bo;
    gemm_mma<<<dim3(DM / 128, TOK / 128, 1), 256, GEMM_SMEM>>>(
        pAhi, pAlo, pWhi + 3 * (size_t)DM * DM, pWlo + 3 * (size_t)DM * DM, g1, -1);
}

// round 14
// speedup vs baseline: 1.1100x; 1.0002x over previous
#include <cuda_runtime.h>
#include <cuda_bf16.h>
#include <math.h>
#include <stdint.h>

// Problem constants: bs=2, seq=2048, d_model=512, heads=8, d_k=64
#define DM     512
#define HEADS  8
#define DK     64
#define SEQ    2048
#define BS     2
#define TOK    (SEQ*BS)     // 4096

// ---------------- scratch (device globals; no allocations allowed) -------------
__device__ float g_Q[TOK * DM];
__device__ float g_K[TOK * DM];
__device__ float g_V[TOK * DM];
__device__ __nv_bfloat16 g_ahi[3 * TOK * DM];
__device__ __nv_bfloat16 g_alo[3 * TOK * DM];
__device__ __nv_bfloat16 g_wthi[4][DM * DM];   // transposed weights [N,K], hi part
__device__ __nv_bfloat16 g_wtlo[4][DM * DM];   // lo part
__device__ float g_vsum[BS * DM];

struct WIn  { const float* W[4]; };
struct CIn  { const float* x[3]; };
struct GOut { float* C[3]; const float* bias[3]; };

// ================= helpers ======================================================
__device__ __forceinline__ uint32_t smem_u32(const void* p) {
    uint32_t a;
    asm("{ .reg .u64 t; cvta.to.shared.u64 t, %1; cvt.u32.u64 %0, t; }" : "=r"(a) : "l"(p));
    return a;
}
__device__ __forceinline__ uint32_t sw128(uint32_t o) { return o ^ ((o >> 3) & 0x70); }

__device__ __forceinline__ void cp16(uint32_t dst, const void* src) {
    asm volatile("cp.async.cg.shared.global [%0], [%1], 16;" :: "r"(dst), "l"(src));
}
__device__ __forceinline__ void ldsm4(uint32_t* r, uint32_t addr) {
    asm volatile("ldmatrix.sync.aligned.m8n8.x4.shared.b16 {%0,%1,%2,%3}, [%4];"
        : "=r"(r[0]), "=r"(r[1]), "=r"(r[2]), "=r"(r[3]) : "r"(addr));
}
__device__ __forceinline__ void mma16816(float* c, const uint32_t* a, uint32_t b0, uint32_t b1) {
    asm volatile("mma.sync.aligned.m16n8k16.row.col.f32.bf16.bf16.f32 "
        "{%0,%1,%2,%3}, {%4,%5,%6,%7}, {%8,%9}, {%0,%1,%2,%3};"
        : "+f"(c[0]), "+f"(c[1]), "+f"(c[2]), "+f"(c[3])
        : "r"(a[0]), "r"(a[1]), "r"(a[2]), "r"(a[3]), "r"(b0), "r"(b1));
}

// ================= bf16-split mma.sync GEMM (at legacy-HMMA roofline) ===========
#define KC      64
#define NKC     (DM / KC)               // 8
#define TILE_B  (128 * 128)             // 16 KB per array per stage
#define STG_B   (4 * TILE_B)            // 64 KB per stage
#define GEMM_SMEM (2 * STG_B)           // 131072

__global__ void __launch_bounds__(256, 1)
gemm_mma(const __nv_bfloat16* __restrict__ Ahi_base, const __nv_bfloat16* __restrict__ Alo_base,
         const __nv_bfloat16* __restrict__ Whi_base, const __nv_bfloat16* __restrict__ Wlo_base,
         GOut outs, int vsum_z)
{
    extern __shared__ char smem[];
    const uint32_t sb = smem_u32(smem);
    const int tid  = threadIdx.x;
    const int wid  = tid >> 5;
    const int lane = tid & 31;
    const int m0   = blockIdx.y * 128;
    const int n0   = blockIdx.x * 128;
    const int z    = blockIdx.z;

    const __nv_bfloat16* arrs[4] = {
        Ahi_base + (size_t)z * TOK * DM, Alo_base + (size_t)z * TOK * DM,
        Whi_base + (size_t)z * DM * DM,  Wlo_base + (size_t)z * DM * DM };
    float* C = outs.C[z];
    const float* bias = outs.bias[z];

    const int lrow = tid >> 1;
    const int lc0  = (tid & 1) * 4;

    auto load_stage = [&](int kc, int s) {
        const uint32_t stg = sb + s * STG_B;
        #pragma unroll
        for (int a = 0; a < 4; a++) {
            const int grow = ((a < 2) ? m0 : n0) + lrow;
            const __nv_bfloat16* src = arrs[a] + (size_t)grow * DM + kc * KC + lc0 * 8;
            const uint32_t abase = stg + a * TILE_B;
            #pragma unroll
            for (int c = 0; c < 4; c++)
                cp16(abase + sw128(lrow * 128 + (lc0 + c) * 16), src + c * 8);
        }
        asm volatile("cp.async.commit_group;" ::: "memory");
    };

    load_stage(0, 0);
    load_stage(1, 1);

    const int wm = (wid & 1) * 64;
    const int wn = (wid >> 1) * 32;
    const int lane8 = lane & 7;
    const int rowp8 = ((lane >> 3) & 1) * 8;
    const int kp1   = (lane >> 4) & 1;

    float acc[4][4][4];
    #pragma unroll
    for (int f = 0; f < 4; f++)
        #pragma unroll
        for (int n = 0; n < 4; n++)
            #pragma unroll
            for (int e = 0; e < 4; e++) acc[f][n][e] = 0.f;

    for (int kc = 0; kc < NKC; kc++) {
        const int s = kc & 1;
        if (kc < NKC - 1) asm volatile("cp.async.wait_group 1;" ::: "memory");
        else              asm volatile("cp.async.wait_group 0;" ::: "memory");
        __syncthreads();

        const uint32_t sAh = sb + s * STG_B + 0 * TILE_B;
        const uint32_t sAl = sb + s * STG_B + 1 * TILE_B;
        const uint32_t sBh = sb + s * STG_B + 2 * TILE_B;
        const uint32_t sBl = sb + s * STG_B + 3 * TILE_B;

        #pragma unroll
        for (int kk = 0; kk < KC / 16; kk++) {
            const int ch = kk * 2 + kp1;
            uint32_t bh[2][4], bl[2][4];
            #pragma unroll
            for (int p = 0; p < 2; p++) {
                const uint32_t off = sw128((wn + p * 16 + lane8 + rowp8) * 128 + ch * 16);
                ldsm4(bh[p], sBh + off);
                ldsm4(bl[p], sBl + off);
            }
            uint32_t ah[4][4], al[4][4];
            #pragma unroll
            for (int f = 0; f < 4; f++) {
                const uint32_t off = sw128((wm + f * 16 + lane8 + rowp8) * 128 + ch * 16);
                ldsm4(ah[f], sAh + off);
                ldsm4(al[f], sAl + off);
            }
            #pragma unroll
            for (int f = 0; f < 4; f++)
                #pragma unroll
                for (int p = 0; p < 2; p++) {
                    mma16816(acc[f][2 * p + 0], ah[f], bh[p][0], bh[p][2]);
                    mma16816(acc[f][2 * p + 1], ah[f], bh[p][1], bh[p][3]);
                }
            #pragma unroll
            for (int f = 0; f < 4; f++)
                #pragma unroll
                for (int p = 0; p < 2; p++) {
                    mma16816(acc[f][2 * p + 0], ah[f], bl[p][0], bl[p][2]);
                    mma16816(acc[f][2 * p + 1], ah[f], bl[p][1], bl[p][3]);
                }
            #pragma unroll
            for (int f = 0; f < 4; f++)
                #pragma unroll
                for (int p = 0; p < 2; p++) {
                    mma16816(acc[f][2 * p + 0], al[f], bh[p][0], bh[p][2]);
                    mma16816(acc[f][2 * p + 1], al[f], bh[p][1], bh[p][3]);
                }
        }
        __syncthreads();
        if (kc + 2 < NKC) load_stage(kc + 2, s);
    }

    const int row0 = m0 + wm + (lane >> 2);
    const int colb = n0 + wn + (lane & 3) * 2;
    float cs0[4], cs1[4];
    #pragma unroll
    for (int n = 0; n < 4; n++) { cs0[n] = 0.f; cs1[n] = 0.f; }

    #pragma unroll
    for (int f = 0; f < 4; f++) {
        #pragma unroll
        for (int n = 0; n < 4; n++) {
            const int col = colb + n * 8;
            const float2 bv = *(const float2*)(bias + col);
            float2 o0, o1;
            o0.x = acc[f][n][0] + bv.x; o0.y = acc[f][n][1] + bv.y;
            o1.x = acc[f][n][2] + bv.x; o1.y = acc[f][n][3] + bv.y;
            cs0[n] += o0.x + o1.x;
            cs1[n] += o0.y + o1.y;
            *(float2*)(C + (size_t)(row0 + f * 16 + 0) * DM + col) = o0;
            *(float2*)(C + (size_t)(row0 + f * 16 + 8) * DM + col) = o1;
        }
    }

    if (z == vsum_z) {
        #pragma unroll
        for (int n = 0; n < 4; n++) {
            #pragma unroll
            for (int o = 4; o <= 16; o <<= 1) {
                cs0[n] += __shfl_xor_sync(0xffffffffu, cs0[n], o);
                cs1[n] += __shfl_xor_sync(0xffffffffu, cs1[n], o);
            }
        }
        if (lane < 4) {
            const int b = m0 / SEQ;
            #pragma unroll
            for (int n = 0; n < 4; n++) {
                const int col = n0 + wn + (lane & 3) * 2 + n * 8;
                atomicAdd(&g_vsum[b * DM + col + 0], cs0[n]);
                atomicAdd(&g_vsum[b * DM + col + 1], cs1[n]);
            }
        }
    }
}

// ================= merged prep: weight transpose + activation split =============
// blocks [0, 1024): weight transpose+split (4 weights x 256 tiles)
// blocks [1024, 1024+3*2048): activation fp32 -> bf16 hi/lo (q,k,v)
#define CVG  (TOK * DM / 4 / 256)      // 2048 blocks per activation
__global__ void __launch_bounds__(256)
prep(WIn win, CIn cin, __nv_bfloat16* __restrict__ hi, __nv_bfloat16* __restrict__ lo,
     __nv_bfloat16* __restrict__ whi, __nv_bfloat16* __restrict__ wlo)
{
    const int blk = blockIdx.x;
    const int tid = threadIdx.x;

    if (blk < 1024) {
        // ---- weight transpose path ----
        __shared__ float t[32][33];
        const int z  = blk >> 8;
        const int tl = blk & 255;
        const int bx = (tl & 15) * 32;   // n
        const int by = (tl >> 4) * 32;   // k
        const int x = tid & 31, y = tid >> 5;
        const float* W = win.W[z];
        __nv_bfloat16* ho  = whi + (size_t)z * DM * DM;
        __nv_bfloat16* lo2 = wlo + (size_t)z * DM * DM;

        if (blk == 0) {
            #pragma unroll
            for (int r = 0; r < BS * DM / 256; r++) g_vsum[tid + r * 256] = 0.f;
        }

        #pragma unroll
        for (int r = y; r < 32; r += 8)
            t[r][x] = W[(size_t)(by + r) * DM + bx + x];
        __syncthreads();
        #pragma unroll
        for (int i = y; i < 32; i += 8) {
            float v = t[x][i];
            __nv_bfloat16 h = __float2bfloat16_rn(v);
            __nv_bfloat16 l = __float2bfloat16_rn(v - __bfloat162float(h));
            size_t o = (size_t)(bx + i) * DM + by + x;
            ho[o] = h;
            lo2[o] = l;
        }
    } else {
        // ---- activation split path ----
        const int idx = blk - 1024;
        const int z   = idx / CVG;
        const size_t i = (size_t)(idx % CVG) * 256 + tid;
        const size_t o = (size_t)z * (TOK * DM / 4) + i;
        float4 v = ((const float4*)cin.x[z])[i];
        __nv_bfloat16 h[4], l[4];
        float f[4] = { v.x, v.y, v.z, v.w };
        #pragma unroll
        for (int t2 = 0; t2 < 4; t2++) {
            h[t2] = __float2bfloat16_rn(f[t2]);
            l[t2] = __float2bfloat16_rn(f[t2] - __bfloat162float(h[t2]));
        }
        ((ushort4*)hi)[o] = make_ushort4(__bfloat16_as_ushort(h[0]), __bfloat16_as_ushort(h[1]),
                                         __bfloat16_as_ushort(h[2]), __bfloat16_as_ushort(h[3]));
        ((ushort4*)lo)[o] = make_ushort4(__bfloat16_as_ushort(l[0]), __bfloat16_as_ushort(l[1]),
                                         __bfloat16_as_ushort(l[2]), __bfloat16_as_ushort(l[3]));
    }
}

// ================= banded attention (closed-form full-row softmax) ==============
// 8 lanes per row; each warp handles 8 rows as two 4-row groups (A: i0+sub,
// B: i0+sub+4) sharing the 13 band K/V row loads. Edge warps take generic path.

__device__ __forceinline__ void attn_store_row(
    float* r, float w0, float rZ, const float* vsp, size_t o,
    __nv_bfloat16* chi, __nv_bfloat16* clo)
{
    const float4 vs0 = *(const float4*)vsp;
    const float4 vs1 = *(const float4*)(vsp + 4);
    r[0] = (r[0] + w0 * vs0.x) * rZ;
    r[1] = (r[1] + w0 * vs0.y) * rZ;
    r[2] = (r[2] + w0 * vs0.z) * rZ;
    r[3] = (r[3] + w0 * vs0.w) * rZ;
    r[4] = (r[4] + w0 * vs1.x) * rZ;
    r[5] = (r[5] + w0 * vs1.y) * rZ;
    r[6] = (r[6] + w0 * vs1.z) * rZ;
    r[7] = (r[7] + w0 * vs1.w) * rZ;
    ushort hb8[8], lb8[8];
    #pragma unroll
    for (int c = 0; c < 8; c++) {
        const __nv_bfloat16 hb = __float2bfloat16_rn(r[c]);
        hb8[c] = __bfloat16_as_ushort(hb);
        lb8[c] = __bfloat16_as_ushort(__float2bfloat16_rn(r[c] - __bfloat162float(hb)));
    }
    uint4 uh, ul;
    uh.x = (uint32_t)hb8[0] | ((uint32_t)hb8[1] << 16);
    uh.y = (uint32_t)hb8[2] | ((uint32_t)hb8[3] << 16);
    uh.z = (uint32_t)hb8[4] | ((uint32_t)hb8[5] << 16);
    uh.w = (uint32_t)hb8[6] | ((uint32_t)hb8[7] << 16);
    ul.x = (uint32_t)lb8[0] | ((uint32_t)lb8[1] << 16);
    ul.y = (uint32_t)lb8[2] | ((uint32_t)lb8[3] << 16);
    ul.z = (uint32_t)lb8[4] | ((uint32_t)lb8[5] << 16);
    ul.w = (uint32_t)lb8[6] | ((uint32_t)lb8[7] << 16);
    *(uint4*)(chi + o) = uh;
    *(uint4*)(clo + o) = ul;
}

__device__ __forceinline__ void attn_row_generic(
    int i, size_t base, const float* Q, const float* K, const float* V,
    const float* vsp, __nv_bfloat16* chi, __nv_bfloat16* clo)
{
    const float* qp = Q + base + (size_t)i * DM;
    const float4 q0 = *(const float4*)qp;
    const float4 q1 = *(const float4*)(qp + 4);

    const int jlo = max(i - 4, 0);
    const int jhi = min(i + 4, SEQ - 1);
    const int nb  = jhi - jlo + 1;

    float s[9], smax = 0.f;
    #pragma unroll
    for (int t = 0; t < 9; t++) {
        const int j = jlo + t;
        const bool valid = (j <= jhi);
        const int jc = valid ? j : jhi;
        const float* kp = K + base + (size_t)jc * DM;
        const float4 k0 = *(const float4*)kp;
        const float4 k1 = *(const float4*)(kp + 4);
        float p = q0.x * k0.x + q0.y * k0.y + q0.z * k0.z + q0.w * k0.w
                + q1.x * k1.x + q1.y * k1.y + q1.z * k1.z + q1.w * k1.w;
        p += __shfl_xor_sync(0xffffffffu, p, 1);
        p += __shfl_xor_sync(0xffffffffu, p, 2);
        p += __shfl_xor_sync(0xffffffffu, p, 4);
        const int mn = min(i, j), mx = max(i, j);
        const int clo2 = max(mx - 2, 0);
        const int chi2 = min(mn + 2, SEQ - 1);
        s[t] = valid ? p * 0.125f * (float)(chi2 - clo2 + 1) : -1e30f;
        smax = fmaxf(smax, s[t]);
    }

    const float w0 = __expf(-smax);
    float Z = (float)(SEQ - nb) * w0;
    #pragma unroll
    for (int t = 0; t < 9; t++) { s[t] = __expf(s[t] - smax); Z += s[t]; }
    const float rZ = 1.f / Z;

    float r[8];
    #pragma unroll
    for (int c = 0; c < 8; c++) r[c] = 0.f;
    const float* vp = V + base + (size_t)jlo * DM;
    #pragma unroll
    for (int t = 0; t < 9; t++) {
        const float wt = (t < nb) ? (s[t] - w0) : 0.f;
        const float4 v0 = *(const float4*)vp;
        const float4 v1 = *(const float4*)(vp + 4);
        if (t < nb - 1) vp += DM;
        r[0] += wt * v0.x; r[1] += wt * v0.y; r[2] += wt * v0.z; r[3] += wt * v0.w;
        r[4] += wt * v1.x; r[5] += wt * v1.y; r[6] += wt * v1.z; r[7] += wt * v1.w;
    }
    attn_store_row(r, w0, rZ, vsp, base + (size_t)i * DM, chi, clo);
}

__global__ __launch_bounds__(256)
void attn_kernel(const float* __restrict__ Q, const float* __restrict__ K,
                 const float* __restrict__ V,
                 __nv_bfloat16* __restrict__ chi, __nv_bfloat16* __restrict__ clo)
{
    const int lane = threadIdx.x & 31;
    const int wid  = threadIdx.x >> 5;
    const int sub  = lane >> 3;          // 0..3
    const int sl   = lane & 7;           // dim slice, 8 floats each

    const int row0 = blockIdx.x * 64 + wid * 8;   // warp's first row_id
    const int i0   = row0 & (SEQ - 1);
    const int bh   = row0 >> 11;
    const int h    = bh & (HEADS - 1);
    const int b    = bh >> 3;

    const size_t base = ((size_t)b * SEQ) * DM + h * DK + sl * 8;
    const float* vsp  = g_vsum + b * DM + h * DK + sl * 8;

    const int iA = i0 + sub;
    const int iB = iA + 4;

    if (i0 >= 4 && i0 + 11 <= SEQ - 1) {
        // -------- interior fast path: shared band loads for two row groups -----
        const float* qpA = Q + base + (size_t)iA * DM;
        const float* qpB = Q + base + (size_t)iB * DM;
        const float4 qA0 = *(const float4*)qpA;
        const float4 qA1 = *(const float4*)(qpA + 4);
        const float4 qB0 = *(const float4*)qpB;
        const float4 qB1 = *(const float4*)(qpB + 4);

        float sA[9], sB[9];
        float smA = 0.f, smB = 0.f;
        const float* kp = K + base + (size_t)(iA - 4) * DM;
        #pragma unroll
        for (int t = 0; t < 13; t++) {
            const float4 k0 = *(const float4*)kp;
            const float4 k1 = *(const float4*)(kp + 4);
            kp += DM;
            if (t < 9) {
                float p = qA0.x * k0.x + qA0.y * k0.y + qA0.z * k0.z + qA0.w * k0.w
                        + qA1.x * k1.x + qA1.y * k1.y + qA1.z * k1.z + qA1.w * k1.w;
                p += __shfl_xor_sync(0xffffffffu, p, 1);
                p += __shfl_xor_sync(0xffffffffu, p, 2);
                p += __shfl_xor_sync(0xffffffffu, p, 4);
                const float cc = (float)(5 - ((t > 4) ? (t - 4) : (4 - t)));
                sA[t] = p * 0.125f * cc;
                smA = fmaxf(smA, sA[t]);
            }
            if (t >= 4) {
                const int u = t - 4;
                float p = qB0.x * k0.x + qB0.y * k0.y + qB0.z * k0.z + qB0.w * k0.w
                        + qB1.x * k1.x + qB1.y * k1.y + qB1.z * k1.z + qB1.w * k1.w;
                p += __shfl_xor_sync(0xffffffffu, p, 1);
                p += __shfl_xor_sync(0xffffffffu, p, 2);
                p += __shfl_xor_sync(0xffffffffu, p, 4);
                const float cc = (float)(5 - ((u > 4) ? (u - 4) : (4 - u)));
                sB[u] = p * 0.125f * cc;
                smB = fmaxf(smB, sB[u]);
            }
        }

        const float w0A = __expf(-smA);
        const float w0B = __expf(-smB);
        float ZA = (float)(SEQ - 9) * w0A;
        float ZB = (float)(SEQ - 9) * w0B;
        #pragma unroll
        for (int t = 0; t < 9; t++) {
            sA[t] = __expf(sA[t] - smA); ZA += sA[t];
            sB[t] = __expf(sB[t] - smB); ZB += sB[t];
        }
        const float rZA = 1.f / ZA;
        const float rZB = 1.f / ZB;

        float rA[8], rB[8];
        #pragma unroll
        for (int c = 0; c < 8; c++) { rA[c] = 0.f; rB[c] = 0.f; }
        const float* vp = V + base + (size_t)(iA - 4) * DM;
        #pragma unroll
        for (int t = 0; t < 13; t++) {
            const float4 v0 = *(const float4*)vp;
            const float4 v1 = *(const float4*)(vp + 4);
            vp += DM;
            if (t < 9) {
                const float wt = sA[t] - w0A;
                rA[0] += wt * v0.x; rA[1] += wt * v0.y; rA[2] += wt * v0.z; rA[3] += wt * v0.w;
                rA[4] += wt * v1.x; rA[5] += wt * v1.y; rA[6] += wt * v1.z; rA[7] += wt * v1.w;
            }
            if (t >= 4) {
                const float wt = sB[t - 4] - w0B;
                rB[0] += wt * v0.x; rB[1] += wt * v0.y; rB[2] += wt * v0.z; rB[3] += wt * v0.w;
                rB[4] += wt * v1.x; rB[5] += wt * v1.y; rB[6] += wt * v1.z; rB[7] += wt * v1.w;
            }
        }

        attn_store_row(rA, w0A, rZA, vsp, base + (size_t)iA * DM, chi, clo);
        attn_store_row(rB, w0B, rZB, vsp, base + (size_t)iB * DM, chi, clo);
    } else {
        // -------- edge path (2 warps per (b,h)) --------------------------------
        attn_row_generic(iA, base, Q, K, V, vsp, chi, clo);
        attn_row_generic(iB, base, Q, K, V, vsp, chi, clo);
    }
}

// ================= launch =======================================================
extern "C" void kernel_launch(void* const* d_in, const int* in_sizes, int n_in,
                              void* d_out, int out_size)
{
    const float* q  = (const float*)d_in[0];
    const float* k  = (const float*)d_in[1];
    const float* v  = (const float*)d_in[2];
    const float* Wq = (const float*)d_in[3];
    const float* bq = (const float*)d_in[4];
    const float* Wk = (const float*)d_in[5];
    const float* bk = (const float*)d_in[6];
    const float* Wv = (const float*)d_in[7];
    const float* bv = (const float*)d_in[8];
    const float* Wo = (const float*)d_in[9];
    const float* bo = (const float*)d_in[10];
    float* out = (float*)d_out;

    float *pQ, *pK, *pV;
    __nv_bfloat16 *pAhi, *pAlo, *pWhi, *pWlo;
    cudaGetSymbolAddress((void**)&pQ,   g_Q);
    cudaGetSymbolAddress((void**)&pK,   g_K);
    cudaGetSymbolAddress((void**)&pV,   g_V);
    cudaGetSymbolAddress((void**)&pAhi, g_ahi);
    cudaGetSymbolAddress((void**)&pAlo, g_alo);
    cudaGetSymbolAddress((void**)&pWhi, g_wthi);
    cudaGetSymbolAddress((void**)&pWlo, g_wtlo);

    cudaFuncSetAttribute(gemm_mma, cudaFuncAttributeMaxDynamicSharedMemorySize, GEMM_SMEM);

    // merged prep: weight transpose + q/k/v bf16 split + g_vsum zero, one launch
    WIn win; win.W[0] = Wq; win.W[1] = Wk; win.W[2] = Wv; win.W[3] = Wo;
    CIn cin; cin.x[0] = q; cin.x[1] = k; cin.x[2] = v;
    prep<<<1024 + 3 * CVG, 256>>>(win, cin, pAhi, pAlo, pWhi, pWlo);

    // Q,K,V projections in one batched launch; V (z=2) fuses column-sum
    GOut g3;
    g3.C[0] = pQ;  g3.C[1] = pK;  g3.C[2] = pV;
    g3.bias[0] = bq; g3.bias[1] = bk; g3.bias[2] = bv;
    gemm_mma<<<dim3(DM / 128, TOK / 128, 3), 256, GEMM_SMEM>>>(pAhi, pAlo, pWhi, pWlo, g3, 2);

    // attention -> ctx written as bf16 hi/lo into activation slot 0
    // 64 rows per block: 32768 / 64 = 512 blocks
    attn_kernel<<<512, 256>>>(pQ, pK, pV, pAhi, pAlo);

    // out = ctx@Wo+bo
    GOut g1;
    g1.C[0] = out; g1.C[1] = out; g1.C[2] = out;
    g1.bias[0] = bo; g1.bias[1] = bo; g1.bias[2] = bo;
    gemm_mma<<<dim3(DM / 128, TOK / 128, 1), 256, GEMM_SMEM>>>(
        pAhi, pAlo, pWhi + 3 * (size_t)DM * DM, pWlo + 3 * (size_t)DM * DM, g1, -1);
}

// round 15
// speedup vs baseline: 1.2620x; 1.1370x over previous
#include <cuda_runtime.h>
#include <cuda_bf16.h>
#include <math.h>
#include <stdint.h>

// Problem constants: bs=2, seq=2048, d_model=512, heads=8, d_k=64
#define DM     512
#define HEADS  8
#define DK     64
#define SEQ    2048
#define BS     2
#define TOK    (SEQ*BS)     // 4096

// ---------------- scratch (device globals; no allocations allowed) -------------
__device__ float g_Q[TOK * DM];
__device__ float g_K[TOK * DM];
__device__ float g_V[TOK * DM];
__device__ __nv_bfloat16 g_ahi[3 * TOK * DM];
__device__ __nv_bfloat16 g_alo[3 * TOK * DM];
__device__ __nv_bfloat16 g_wthi[4][DM * DM];   // transposed weights [N,K], hi part
__device__ __nv_bfloat16 g_wtlo[4][DM * DM];   // lo part
__device__ float g_vsum[BS * DM];

struct WIn  { const float* W[4]; };
struct CIn  { const float* x[3]; };
struct GOut { float* C[3]; const float* bias[3]; };

// ================= helpers ======================================================
__device__ __forceinline__ uint32_t smem_u32(const void* p) {
    uint32_t a;
    asm("{ .reg .u64 t; cvta.to.shared.u64 t, %1; cvt.u32.u64 %0, t; }" : "=r"(a) : "l"(p));
    return a;
}
__device__ __forceinline__ uint32_t sw128(uint32_t o) { return o ^ ((o >> 3) & 0x70); }

__device__ __forceinline__ void cp16(uint32_t dst, const void* src) {
    asm volatile("cp.async.cg.shared.global [%0], [%1], 16;" :: "r"(dst), "l"(src));
}
__device__ __forceinline__ void ldsm4(uint32_t* r, uint32_t addr) {
    asm volatile("ldmatrix.sync.aligned.m8n8.x4.shared.b16 {%0,%1,%2,%3}, [%4];"
        : "=r"(r[0]), "=r"(r[1]), "=r"(r[2]), "=r"(r[3]) : "r"(addr));
}
__device__ __forceinline__ void mma16816(float* c, const uint32_t* a, uint32_t b0, uint32_t b1) {
    asm volatile("mma.sync.aligned.m16n8k16.row.col.f32.bf16.bf16.f32 "
        "{%0,%1,%2,%3}, {%4,%5,%6,%7}, {%8,%9}, {%0,%1,%2,%3};"
        : "+f"(c[0]), "+f"(c[1]), "+f"(c[2]), "+f"(c[3])
        : "r"(a[0]), "r"(a[1]), "r"(a[2]), "r"(a[3]), "r"(b0), "r"(b1));
}

// ================= bf16-split mma.sync GEMM ====================================
// 512 threads / 16 warps (4 warps/SMSP for latency hiding), CTA tile 128x128,
// warp tile 32x32. K chunk 64 (SW128 128B rows), 2-stage cp.async pipeline.
#define KC      64
#define NKC     (DM / KC)               // 8
#define TILE_B  (128 * 128)             // 16 KB per array per stage
#define STG_B   (4 * TILE_B)            // 64 KB per stage
#define GEMM_SMEM (2 * STG_B)           // 131072

__global__ void __launch_bounds__(512, 1)
gemm_mma(const __nv_bfloat16* __restrict__ Ahi_base, const __nv_bfloat16* __restrict__ Alo_base,
         const __nv_bfloat16* __restrict__ Whi_base, const __nv_bfloat16* __restrict__ Wlo_base,
         GOut outs, int vsum_z)
{
    extern __shared__ char smem[];
    const uint32_t sb = smem_u32(smem);
    const int tid  = threadIdx.x;
    const int wid  = tid >> 5;
    const int lane = tid & 31;
    const int m0   = blockIdx.y * 128;
    const int n0   = blockIdx.x * 128;
    const int z    = blockIdx.z;

    const __nv_bfloat16* arrs[4] = {
        Ahi_base + (size_t)z * TOK * DM, Alo_base + (size_t)z * TOK * DM,
        Whi_base + (size_t)z * DM * DM,  Wlo_base + (size_t)z * DM * DM };
    float* C = outs.C[z];
    const float* bias = outs.bias[z];

    // cp.async mapping (512 threads): row tid/4, two 16B chunks (tid&3)*2 .. +1
    const int lrow = tid >> 2;
    const int lc0  = (tid & 3) * 2;

    auto load_stage = [&](int kc, int s) {
        const uint32_t stg = sb + s * STG_B;
        #pragma unroll
        for (int a = 0; a < 4; a++) {
            const int grow = ((a < 2) ? m0 : n0) + lrow;
            const __nv_bfloat16* src = arrs[a] + (size_t)grow * DM + kc * KC + lc0 * 8;
            const uint32_t abase = stg + a * TILE_B;
            #pragma unroll
            for (int c = 0; c < 2; c++)
                cp16(abase + sw128(lrow * 128 + (lc0 + c) * 16), src + c * 8);
        }
        asm volatile("cp.async.commit_group;" ::: "memory");
    };

    load_stage(0, 0);
    load_stage(1, 1);

    // warp tiling: 4 warps in m x 4 warps in n, warp tile 32(m) x 32(n)
    const int wm = (wid & 3) * 32;
    const int wn = (wid >> 2) * 32;
    const int lane8 = lane & 7;
    const int rowp8 = ((lane >> 3) & 1) * 8;
    const int kp1   = (lane >> 4) & 1;

    float acc[2][4][4];
    #pragma unroll
    for (int f = 0; f < 2; f++)
        #pragma unroll
        for (int n = 0; n < 4; n++)
            #pragma unroll
            for (int e = 0; e < 4; e++) acc[f][n][e] = 0.f;

    for (int kc = 0; kc < NKC; kc++) {
        const int s = kc & 1;
        if (kc < NKC - 1) asm volatile("cp.async.wait_group 1;" ::: "memory");
        else              asm volatile("cp.async.wait_group 0;" ::: "memory");
        __syncthreads();

        const uint32_t sAh = sb + s * STG_B + 0 * TILE_B;
        const uint32_t sAl = sb + s * STG_B + 1 * TILE_B;
        const uint32_t sBh = sb + s * STG_B + 2 * TILE_B;
        const uint32_t sBl = sb + s * STG_B + 3 * TILE_B;

        #pragma unroll
        for (int kk = 0; kk < KC / 16; kk++) {
            const int ch = kk * 2 + kp1;
            uint32_t bh[2][4], bl[2][4];
            #pragma unroll
            for (int p = 0; p < 2; p++) {
                const uint32_t off = sw128((wn + p * 16 + lane8 + rowp8) * 128 + ch * 16);
                ldsm4(bh[p], sBh + off);
                ldsm4(bl[p], sBl + off);
            }
            uint32_t ah[2][4], al[2][4];
            #pragma unroll
            for (int f = 0; f < 2; f++) {
                const uint32_t off = sw128((wm + f * 16 + lane8 + rowp8) * 128 + ch * 16);
                ldsm4(ah[f], sAh + off);
                ldsm4(al[f], sAl + off);
            }
            // Pass 1: hi x hi
            #pragma unroll
            for (int f = 0; f < 2; f++)
                #pragma unroll
                for (int p = 0; p < 2; p++) {
                    mma16816(acc[f][2 * p + 0], ah[f], bh[p][0], bh[p][2]);
                    mma16816(acc[f][2 * p + 1], ah[f], bh[p][1], bh[p][3]);
                }
            // Pass 2: hi x lo
            #pragma unroll
            for (int f = 0; f < 2; f++)
                #pragma unroll
                for (int p = 0; p < 2; p++) {
                    mma16816(acc[f][2 * p + 0], ah[f], bl[p][0], bl[p][2]);
                    mma16816(acc[f][2 * p + 1], ah[f], bl[p][1], bl[p][3]);
                }
            // Pass 3: lo x hi
            #pragma unroll
            for (int f = 0; f < 2; f++)
                #pragma unroll
                for (int p = 0; p < 2; p++) {
                    mma16816(acc[f][2 * p + 0], al[f], bh[p][0], bh[p][2]);
                    mma16816(acc[f][2 * p + 1], al[f], bh[p][1], bh[p][3]);
                }
        }
        __syncthreads();
        if (kc + 2 < NKC) load_stage(kc + 2, s);
    }

    // epilogue (post-bias), optional fused column-sum for V
    const int row0 = m0 + wm + (lane >> 2);
    const int colb = n0 + wn + (lane & 3) * 2;
    float cs0[4], cs1[4];
    #pragma unroll
    for (int n = 0; n < 4; n++) { cs0[n] = 0.f; cs1[n] = 0.f; }

    #pragma unroll
    for (int f = 0; f < 2; f++) {
        #pragma unroll
        for (int n = 0; n < 4; n++) {
            const int col = colb + n * 8;
            const float2 bv = *(const float2*)(bias + col);
            float2 o0, o1;
            o0.x = acc[f][n][0] + bv.x; o0.y = acc[f][n][1] + bv.y;
            o1.x = acc[f][n][2] + bv.x; o1.y = acc[f][n][3] + bv.y;
            cs0[n] += o0.x + o1.x;
            cs1[n] += o0.y + o1.y;
            *(float2*)(C + (size_t)(row0 + f * 16 + 0) * DM + col) = o0;
            *(float2*)(C + (size_t)(row0 + f * 16 + 8) * DM + col) = o1;
        }
    }

    if (z == vsum_z) {
        #pragma unroll
        for (int n = 0; n < 4; n++) {
            #pragma unroll
            for (int o = 4; o <= 16; o <<= 1) {
                cs0[n] += __shfl_xor_sync(0xffffffffu, cs0[n], o);
                cs1[n] += __shfl_xor_sync(0xffffffffu, cs1[n], o);
            }
        }
        if (lane < 4) {
            const int b = m0 / SEQ;
            #pragma unroll
            for (int n = 0; n < 4; n++) {
                const int col = n0 + wn + (lane & 3) * 2 + n * 8;
                atomicAdd(&g_vsum[b * DM + col + 0], cs0[n]);
                atomicAdd(&g_vsum[b * DM + col + 1], cs1[n]);
            }
        }
    }
}

// ================= merged prep: weight transpose + activation split =============
#define CVG  (TOK * DM / 4 / 256)      // 2048 blocks per activation
__global__ void __launch_bounds__(256)
prep(WIn win, CIn cin, __nv_bfloat16* __restrict__ hi, __nv_bfloat16* __restrict__ lo,
     __nv_bfloat16* __restrict__ whi, __nv_bfloat16* __restrict__ wlo)
{
    const int blk = blockIdx.x;
    const int tid = threadIdx.x;

    if (blk < 1024) {
        __shared__ float t[32][33];
        const int z  = blk >> 8;
        const int tl = blk & 255;
        const int bx = (tl & 15) * 32;   // n
        const int by = (tl >> 4) * 32;   // k
        const int x = tid & 31, y = tid >> 5;
        const float* W = win.W[z];
        __nv_bfloat16* ho  = whi + (size_t)z * DM * DM;
        __nv_bfloat16* lo2 = wlo + (size_t)z * DM * DM;

        if (blk == 0) {
            #pragma unroll
            for (int r = 0; r < BS * DM / 256; r++) g_vsum[tid + r * 256] = 0.f;
        }

        #pragma unroll
        for (int r = y; r < 32; r += 8)
            t[r][x] = W[(size_t)(by + r) * DM + bx + x];
        __syncthreads();
        #pragma unroll
        for (int i = y; i < 32; i += 8) {
            float v = t[x][i];
            __nv_bfloat16 h = __float2bfloat16_rn(v);
            __nv_bfloat16 l = __float2bfloat16_rn(v - __bfloat162float(h));
            size_t o = (size_t)(bx + i) * DM + by + x;
            ho[o] = h;
            lo2[o] = l;
        }
    } else {
        const int idx = blk - 1024;
        const int z   = idx / CVG;
        const size_t i = (size_t)(idx % CVG) * 256 + tid;
        const size_t o = (size_t)z * (TOK * DM / 4) + i;
        float4 v = ((const float4*)cin.x[z])[i];
        __nv_bfloat16 h[4], l[4];
        float f[4] = { v.x, v.y, v.z, v.w };
        #pragma unroll
        for (int t2 = 0; t2 < 4; t2++) {
            h[t2] = __float2bfloat16_rn(f[t2]);
            l[t2] = __float2bfloat16_rn(f[t2] - __bfloat162float(h[t2]));
        }
        ((ushort4*)hi)[o] = make_ushort4(__bfloat16_as_ushort(h[0]), __bfloat16_as_ushort(h[1]),
                                         __bfloat16_as_ushort(h[2]), __bfloat16_as_ushort(h[3]));
        ((ushort4*)lo)[o] = make_ushort4(__bfloat16_as_ushort(l[0]), __bfloat16_as_ushort(l[1]),
                                         __bfloat16_as_ushort(l[2]), __bfloat16_as_ushort(l[3]));
    }
}

// ================= banded attention (closed-form full-row softmax) ==============
__device__ __forceinline__ void attn_store_row(
    float* r, float w0, float rZ, const float* vsp, size_t o,
    __nv_bfloat16* chi, __nv_bfloat16* clo)
{
    const float4 vs0 = *(const float4*)vsp;
    const float4 vs1 = *(const float4*)(vsp + 4);
    r[0] = (r[0] + w0 * vs0.x) * rZ;
    r[1] = (r[1] + w0 * vs0.y) * rZ;
    r[2] = (r[2] + w0 * vs0.z) * rZ;
    r[3] = (r[3] + w0 * vs0.w) * rZ;
    r[4] = (r[4] + w0 * vs1.x) * rZ;
    r[5] = (r[5] + w0 * vs1.y) * rZ;
    r[6] = (r[6] + w0 * vs1.z) * rZ;
    r[7] = (r[7] + w0 * vs1.w) * rZ;
    ushort hb8[8], lb8[8];
    #pragma unroll
    for (int c = 0; c < 8; c++) {
        const __nv_bfloat16 hb = __float2bfloat16_rn(r[c]);
        hb8[c] = __bfloat16_as_ushort(hb);
        lb8[c] = __bfloat16_as_ushort(__float2bfloat16_rn(r[c] - __bfloat162float(hb)));
    }
    uint4 uh, ul;
    uh.x = (uint32_t)hb8[0] | ((uint32_t)hb8[1] << 16);
    uh.y = (uint32_t)hb8[2] | ((uint32_t)hb8[3] << 16);
    uh.z = (uint32_t)hb8[4] | ((uint32_t)hb8[5] << 16);
    uh.w = (uint32_t)hb8[6] | ((uint32_t)hb8[7] << 16);
    ul.x = (uint32_t)lb8[0] | ((uint32_t)lb8[1] << 16);
    ul.y = (uint32_t)lb8[2] | ((uint32_t)lb8[3] << 16);
    ul.z = (uint32_t)lb8[4] | ((uint32_t)lb8[5] << 16);
    ul.w = (uint32_t)lb8[6] | ((uint32_t)lb8[7] << 16);
    *(uint4*)(chi + o) = uh;
    *(uint4*)(clo + o) = ul;
}

__device__ __forceinline__ void attn_row_generic(
    int i, size_t base, const float* Q, const float* K, const float* V,
    const float* vsp, __nv_bfloat16* chi, __nv_bfloat16* clo)
{
    const float* qp = Q + base + (size_t)i * DM;
    const float4 q0 = *(const float4*)qp;
    const float4 q1 = *(const float4*)(qp + 4);

    const int jlo = max(i - 4, 0);
    const int jhi = min(i + 4, SEQ - 1);
    const int nb  = jhi - jlo + 1;

    float s[9], smax = 0.f;
    #pragma unroll
    for (int t = 0; t < 9; t++) {
        const int j = jlo + t;
        const bool valid = (j <= jhi);
        const int jc = valid ? j : jhi;
        const float* kp = K + base + (size_t)jc * DM;
        const float4 k0 = *(const float4*)kp;
        const float4 k1 = *(const float4*)(kp + 4);
        float p = q0.x * k0.x + q0.y * k0.y + q0.z * k0.z + q0.w * k0.w
                + q1.x * k1.x + q1.y * k1.y + q1.z * k1.z + q1.w * k1.w;
        p += __shfl_xor_sync(0xffffffffu, p, 1);
        p += __shfl_xor_sync(0xffffffffu, p, 2);
        p += __shfl_xor_sync(0xffffffffu, p, 4);
        const int mn = min(i, j), mx = max(i, j);
        const int clo2 = max(mx - 2, 0);
        const int chi2 = min(mn + 2, SEQ - 1);
        s[t] = valid ? p * 0.125f * (float)(chi2 - clo2 + 1) : -1e30f;
        smax = fmaxf(smax, s[t]);
    }

    const float w0 = __expf(-smax);
    float Z = (float)(SEQ - nb) * w0;
    #pragma unroll
    for (int t = 0; t < 9; t++) { s[t] = __expf(s[t] - smax); Z += s[t]; }
    const float rZ = 1.f / Z;

    float r[8];
    #pragma unroll
    for (int c = 0; c < 8; c++) r[c] = 0.f;
    const float* vp = V + base + (size_t)jlo * DM;
    #pragma unroll
    for (int t = 0; t < 9; t++) {
        const float wt = (t < nb) ? (s[t] - w0) : 0.f;
        const float4 v0 = *(const float4*)vp;
        const float4 v1 = *(const float4*)(vp + 4);
        if (t < nb - 1) vp += DM;
        r[0] += wt * v0.x; r[1] += wt * v0.y; r[2] += wt * v0.z; r[3] += wt * v0.w;
        r[4] += wt * v1.x; r[5] += wt * v1.y; r[6] += wt * v1.z; r[7] += wt * v1.w;
    }
    attn_store_row(r, w0, rZ, vsp, base + (size_t)i * DM, chi, clo);
}

__global__ __launch_bounds__(256)
void attn_kernel(const float* __restrict__ Q, const float* __restrict__ K,
                 const float* __restrict__ V,
                 __nv_bfloat16* __restrict__ chi, __nv_bfloat16* __restrict__ clo)
{
    const int lane = threadIdx.x & 31;
    const int wid  = threadIdx.x >> 5;
    const int sub  = lane >> 3;          // 0..3
    const int sl   = lane & 7;           // dim slice, 8 floats each

    const int row0 = blockIdx.x * 64 + wid * 8;
    const int i0   = row0 & (SEQ - 1);
    const int bh   = row0 >> 11;
    const int h    = bh & (HEADS - 1);
    const int b    = bh >> 3;

    const size_t base = ((size_t)b * SEQ) * DM + h * DK + sl * 8;
    const float* vsp  = g_vsum + b * DM + h * DK + sl * 8;

    const int iA = i0 + sub;
    const int iB = iA + 4;

    if (i0 >= 4 && i0 + 11 <= SEQ - 1) {
        const float* qpA = Q + base + (size_t)iA * DM;
        const float* qpB = Q + base + (size_t)iB * DM;
        const float4 qA0 = *(const float4*)qpA;
        const float4 qA1 = *(const float4*)(qpA + 4);
        const float4 qB0 = *(const float4*)qpB;
        const float4 qB1 = *(const float4*)(qpB + 4);

        float sA[9], sB[9];
        float smA = 0.f, smB = 0.f;
        const float* kp = K + base + (size_t)(iA - 4) * DM;
        #pragma unroll
        for (int t = 0; t < 13; t++) {
            const float4 k0 = *(const float4*)kp;
            const float4 k1 = *(const float4*)(kp + 4);
            kp += DM;
            if (t < 9) {
                float p = qA0.x * k0.x + qA0.y * k0.y + qA0.z * k0.z + qA0.w * k0.w
                        + qA1.x * k1.x + qA1.y * k1.y + qA1.z * k1.z + qA1.w * k1.w;
                p += __shfl_xor_sync(0xffffffffu, p, 1);
                p += __shfl_xor_sync(0xffffffffu, p, 2);
                p += __shfl_xor_sync(0xffffffffu, p, 4);
                const float cc = (float)(5 - ((t > 4) ? (t - 4) : (4 - t)));
                sA[t] = p * 0.125f * cc;
                smA = fmaxf(smA, sA[t]);
            }
            if (t >= 4) {
                const int u = t - 4;
                float p = qB0.x * k0.x + qB0.y * k0.y + qB0.z * k0.z + qB0.w * k0.w
                        + qB1.x * k1.x + qB1.y * k1.y + qB1.z * k1.z + qB1.w * k1.w;
                p += __shfl_xor_sync(0xffffffffu, p, 1);
                p += __shfl_xor_sync(0xffffffffu, p, 2);
                p += __shfl_xor_sync(0xffffffffu, p, 4);
                const float cc = (float)(5 - ((u > 4) ? (u - 4) : (4 - u)));
                sB[u] = p * 0.125f * cc;
                smB = fmaxf(smB, sB[u]);
            }
        }

        const float w0A = __expf(-smA);
        const float w0B = __expf(-smB);
        float ZA = (float)(SEQ - 9) * w0A;
        float ZB = (float)(SEQ - 9) * w0B;
        #pragma unroll
        for (int t = 0; t < 9; t++) {
            sA[t] = __expf(sA[t] - smA); ZA += sA[t];
            sB[t] = __expf(sB[t] - smB); ZB += sB[t];
        }
        const float rZA = 1.f / ZA;
        const float rZB = 1.f / ZB;

        float rA[8], rB[8];
        #pragma unroll
        for (int c = 0; c < 8; c++) { rA[c] = 0.f; rB[c] = 0.f; }
        const float* vp = V + base + (size_t)(iA - 4) * DM;
        #pragma unroll
        for (int t = 0; t < 13; t++) {
            const float4 v0 = *(const float4*)vp;
            const float4 v1 = *(const float4*)(vp + 4);
            vp += DM;
            if (t < 9) {
                const float wt = sA[t] - w0A;
                rA[0] += wt * v0.x; rA[1] += wt * v0.y; rA[2] += wt * v0.z; rA[3] += wt * v0.w;
                rA[4] += wt * v1.x; rA[5] += wt * v1.y; rA[6] += wt * v1.z; rA[7] += wt * v1.w;
            }
            if (t >= 4) {
                const float wt = sB[t - 4] - w0B;
                rB[0] += wt * v0.x; rB[1] += wt * v0.y; rB[2] += wt * v0.z; rB[3] += wt * v0.w;
                rB[4] += wt * v1.x; rB[5] += wt * v1.y; rB[6] += wt * v1.z; rB[7] += wt * v1.w;
            }
        }

        attn_store_row(rA, w0A, rZA, vsp, base + (size_t)iA * DM, chi, clo);
        attn_store_row(rB, w0B, rZB, vsp, base + (size_t)iB * DM, chi, clo);
    } else {
        attn_row_generic(iA, base, Q, K, V, vsp, chi, clo);
        attn_row_generic(iB, base, Q, K, V, vsp, chi, clo);
    }
}

// ================= launch =======================================================
extern "C" void kernel_launch(void* const* d_in, const int* in_sizes, int n_in,
                              void* d_out, int out_size)
{
    const float* q  = (const float*)d_in[0];
    const float* k  = (const float*)d_in[1];
    const float* v  = (const float*)d_in[2];
    const float* Wq = (const float*)d_in[3];
    const float* bq = (const float*)d_in[4];
    const float* Wk = (const float*)d_in[5];
    const float* bk = (const float*)d_in[6];
    const float* Wv = (const float*)d_in[7];
    const float* bv = (const float*)d_in[8];
    const float* Wo = (const float*)d_in[9];
    const float* bo = (const float*)d_in[10];
    float* out = (float*)d_out;

    float *pQ, *pK, *pV;
    __nv_bfloat16 *pAhi, *pAlo, *pWhi, *pWlo;
    cudaGetSymbolAddress((void**)&pQ,   g_Q);
    cudaGetSymbolAddress((void**)&pK,   g_K);
    cudaGetSymbolAddress((void**)&pV,   g_V);
    cudaGetSymbolAddress((void**)&pAhi, g_ahi);
    cudaGetSymbolAddress((void**)&pAlo, g_alo);
    cudaGetSymbolAddress((void**)&pWhi, g_wthi);
    cudaGetSymbolAddress((void**)&pWlo, g_wtlo);

    cudaFuncSetAttribute(gemm_mma, cudaFuncAttributeMaxDynamicSharedMemorySize, GEMM_SMEM);

    // merged prep: weight transpose + q/k/v bf16 split + g_vsum zero, one launch
    WIn win; win.W[0] = Wq; win.W[1] = Wk; win.W[2] = Wv; win.W[3] = Wo;
    CIn cin; cin.x[0] = q; cin.x[1] = k; cin.x[2] = v;
    prep<<<1024 + 3 * CVG, 256>>>(win, cin, pAhi, pAlo, pWhi, pWlo);

    // Q,K,V projections in one batched launch; V (z=2) fuses column-sum
    GOut g3;
    g3.C[0] = pQ;  g3.C[1] = pK;  g3.C[2] = pV;
    g3.bias[0] = bq; g3.bias[1] = bk; g3.bias[2] = bv;
    gemm_mma<<<dim3(DM / 128, TOK / 128, 3), 512, GEMM_SMEM>>>(pAhi, pAlo, pWhi, pWlo, g3, 2);

    // attention -> ctx written as bf16 hi/lo into activation slot 0
    attn_kernel<<<512, 256>>>(pQ, pK, pV, pAhi, pAlo);

    // out = ctx@Wo+bo
    GOut g1;
    g1.C[0] = out; g1.C[1] = out; g1.C[2] = out;
    g1.bias[0] = bo; g1.bias[1] = bo; g1.bias[2] = bo;
    gemm_mma<<<dim3(DM / 128, TOK / 128, 1), 512, GEMM_SMEM>>>(
        pAhi, pAlo, pWhi + 3 * (size_t)DM * DM, pWlo + 3 * (size_t)DM * DM, g1, -1);
}